// round 5
// baseline (speedup 1.0000x reference)
#include <cuda_runtime.h>
#include <cuda_bf16.h>
#include <cstdint>

// Problem constants
#define BB 2
#define CIN 256
#define HH 96
#define WW 96
#define COUT 256
#define KK2 9
#define HW (HH*WW)                 // 9216
#define MTOT (BB*HW)               // 18432
#define KKTOT (KK2*CIN)            // 2304
#define NGRP 32
#define GCH (COUT/NGRP)            // 8
#define GELEMS (GCH*HW)            // 73728
#define NK16 (KKTOT/16)            // 144 k16 steps
#define NST (KKTOT/32)             // 72 BK=32 stages
#define NMTILE (MTOT/128)          // 144 m tiles

// Scratch (static device memory)
__device__ __align__(128) float    g_off[BB*18*HW];             // offsets  [B,18,H,W]
// A fragments: [k16][mtile*4+wm][mt(2)][hi/lo(2)][128 words = lane*4]
__device__ __align__(128) uint32_t g_Af[(size_t)NK16*576*512];
__device__ __align__(128) uint32_t g_Wfbh[NK16*32*32*2];        // B hi frag order [k16][n8][lane][2]
__device__ __align__(128) uint32_t g_Wfbl[NK16*32*32*2];        // B lo
__device__ __align__(128) float    g_O[(size_t)MTOT*COUT];      // GEMM out (NHWC): [M, Cout]
__device__ __align__(128) float    g_stats[NGRP*BB*2];          // per (b,g): sum, sumsq

// ------------------------------------------------------------- helpers
__device__ __forceinline__ uint32_t pack2_bf16(float a, float b) {
    uint16_t ua = __bfloat16_as_ushort(__float2bfloat16(a));
    uint16_t ub = __bfloat16_as_ushort(__float2bfloat16(b));
    return (uint32_t)ua | ((uint32_t)ub << 16);
}

#define CP_ASYNC16(dst, src) \
    asm volatile("cp.async.cg.shared.global [%0], [%1], 16;" \
                 :: "r"((uint32_t)(dst)), "l"(__cvta_generic_to_global(src)) : "memory")
#define CP_COMMIT() asm volatile("cp.async.commit_group;" ::: "memory")
#define CP_WAIT0()  asm volatile("cp.async.wait_group 0;" ::: "memory")

__device__ __forceinline__ uint32_t smem_u32(const void* p) {
    uint32_t a;
    asm("{ .reg .u64 t; cvta.to.shared.u64 t, %1; cvt.u32.u64 %0, t; }"
        : "=r"(a) : "l"(p));
    return a;
}

#define MMA_BF16(acc, a, b0, b1) \
    asm volatile("mma.sync.aligned.m16n8k16.row.col.f32.bf16.bf16.f32 " \
                 "{%0,%1,%2,%3},{%4,%5,%6,%7},{%8,%9},{%0,%1,%2,%3};" \
                 : "+f"((acc)[0]), "+f"((acc)[1]), "+f"((acc)[2]), "+f"((acc)[3]) \
                 : "r"((a)[0]), "r"((a)[1]), "r"((a)[2]), "r"((a)[3]), \
                   "r"(b0), "r"(b1))

// ---------------------------------------------------------------- offset conv
__global__ void offset_conv_kernel(const float* __restrict__ x,
                                   const float* __restrict__ ow,
                                   const float* __restrict__ ob) {
    __shared__ float xs[6][34];
    __shared__ __align__(16) float ws[9][20];
    const int w0 = blockIdx.x * 32;
    const int h0 = blockIdx.y * 4;
    const int b  = blockIdx.z;
    const int tx = threadIdx.x, ty = threadIdx.y;
    const int tid = ty * 32 + tx;

    float acc[18];
#pragma unroll
    for (int j = 0; j < 18; j++) acc[j] = 0.f;

    const float* xb = x + b * (CIN*HW);

    for (int c = 0; c < CIN; c++) {
        for (int i = tid; i < 6*34; i += 128) {
            int r = i / 34, cc = i % 34;
            int y = h0 - 1 + r, xx = w0 - 1 + cc;
            float v = 0.f;
            if (y >= 0 && y < HH && xx >= 0 && xx < WW) v = xb[c*HW + y*WW + xx];
            xs[r][cc] = v;
        }
        for (int i = tid; i < 162; i += 128) {
            int j = i / 9, t = i % 9;
            ws[t][j] = ow[j*(CIN*9) + c*9 + t];
        }
        __syncthreads();

#pragma unroll
        for (int t = 0; t < 9; t++) {
            float xv = xs[ty + t/3][tx + t%3];
            float4 a0 = *(const float4*)&ws[t][0];
            float4 a1 = *(const float4*)&ws[t][4];
            float4 a2 = *(const float4*)&ws[t][8];
            float4 a3 = *(const float4*)&ws[t][12];
            float  a4 = ws[t][16], a5 = ws[t][17];
            acc[0]  += xv*a0.x; acc[1]  += xv*a0.y; acc[2]  += xv*a0.z; acc[3]  += xv*a0.w;
            acc[4]  += xv*a1.x; acc[5]  += xv*a1.y; acc[6]  += xv*a1.z; acc[7]  += xv*a1.w;
            acc[8]  += xv*a2.x; acc[9]  += xv*a2.y; acc[10] += xv*a2.z; acc[11] += xv*a2.w;
            acc[12] += xv*a3.x; acc[13] += xv*a3.y; acc[14] += xv*a3.z; acc[15] += xv*a3.w;
            acc[16] += xv*a4;   acc[17] += xv*a5;
        }
        __syncthreads();
    }
    const int h = h0 + ty, w = w0 + tx;
#pragma unroll
    for (int j = 0; j < 18; j++)
        g_off[((b*18 + j)*HH + h)*WW + w] = acc[j] + ob[j];
}

// ---------------------------------------------------------------- weight repack (+ stats zero)
__global__ void repack_w_kernel(const float* __restrict__ cw) {
    if (blockIdx.x == 0 && threadIdx.x < NGRP*BB*2) g_stats[threadIdx.x] = 0.f;
    int idx = blockIdx.x * 256 + threadIdx.x;   // over NK16*32*32*2 = 294912
    if (idx >= NK16*32*32*2) return;
    int j    = idx & 1;
    int lane = (idx >> 1) & 31;
    int n8   = (idx >> 6) & 31;
    int k16  = idx >> 11;
    int kk0 = k16*16 + j*8 + 2*(lane & 3);
    int n   = n8*8 + (lane >> 2);
    int c0 = kk0 & 255, tap0 = kk0 >> 8;
    int kk1 = kk0 + 1;
    int c1 = kk1 & 255, tap1 = kk1 >> 8;
    float v0 = cw[(n*CIN + c0)*9 + tap0];
    float v1 = cw[(n*CIN + c1)*9 + tap1];
    float h0 = __bfloat162float(__float2bfloat16(v0));
    float h1 = __bfloat162float(__float2bfloat16(v1));
    g_Wfbh[idx] = pack2_bf16(h0, h1);
    g_Wfbl[idx] = pack2_bf16(v0 - h0, v1 - h1);
}

// ---------------------------------------------------------------- gather/im2col -> A fragments (bf16 hi/lo)
// Block: 32 m's (one wm slice of a GEMM m-tile) x 1 tap x 256 c.
// Phase 1: bilinear gather into smem vals[c][m]. Phase 2: pack into mma
// fragment order and write coalesced 16B stores.
__global__ __launch_bounds__(256) void gather_kernel(const float* __restrict__ x) {
    __shared__ float vals[256*33];
    const int tid = threadIdx.x;
    const int ml = tid & 31, cg = tid >> 5;
    const int mchunk = blockIdx.x;       // 0..575
    const int tap = blockIdx.y;          // 0..8
    const int mtile = mchunk >> 2, wm = mchunk & 3;

    const int m = mchunk*32 + ml;
    const int b = m / HW;
    const int rem = m - b*HW;
    const int h = rem / WW, w = rem - h*WW;

    const int off_base = ((b*18 + 2*tap)*HH + h)*WW + w;
    const float dy = g_off[off_base];
    const float dx = g_off[off_base + HW];

    const float sy = (float)(h - 1 + tap/3) + dy;
    const float sx = (float)(w - 1 + tap%3) + dx;
    const float y0f = floorf(sy), x0f = floorf(sx);
    const float fy = sy - y0f, fx = sx - x0f;
    const int y0 = (int)y0f, x0 = (int)x0f;
    const int y1 = y0 + 1,  x1 = x0 + 1;

    const bool vy0 = (y0 >= 0) && (y0 < HH), vy1 = (y1 >= 0) && (y1 < HH);
    const bool vx0 = (x0 >= 0) && (x0 < WW), vx1 = (x1 >= 0) && (x1 < WW);
    const float w00 = (vy0 && vx0) ? (1.f-fy)*(1.f-fx) : 0.f;
    const float w01 = (vy0 && vx1) ? (1.f-fy)*fx       : 0.f;
    const float w10 = (vy1 && vx0) ? fy*(1.f-fx)       : 0.f;
    const float w11 = (vy1 && vx1) ? fy*fx             : 0.f;

    const int cy0 = min(max(y0,0),HH-1), cy1 = min(max(y1,0),HH-1);
    const int cx0 = min(max(x0,0),WW-1), cx1 = min(max(x1,0),WW-1);
    const int i00 = cy0*WW+cx0, i01 = cy0*WW+cx1, i10 = cy1*WW+cx0, i11 = cy1*WW+cx1;

    const float* xb = x + (size_t)b * (CIN*HW);

#pragma unroll 4
    for (int i = 0; i < 32; i++) {
        const int c = i*8 + cg;
        const float* xp = xb + (size_t)c*HW;
        float v = w00*xp[i00] + w01*xp[i01] + w10*xp[i10] + w11*xp[i11];
        vals[c*33 + ml] = v;
    }
    __syncthreads();

    // Phase 2: writer. tid -> (lane_g, mt, hl, tbit)
    const int lane_g = tid & 31;
    const int mt   = (tid >> 5) & 1;
    const int hl   = (tid >> 6) & 1;
    const int tbit = (tid >> 7) & 1;
    const int mlb = mt*16 + (lane_g >> 2);
    const int kb  = 2*(lane_g & 3);
    const size_t blk576 = (size_t)mtile*4 + wm;

#pragma unroll
    for (int step = 0; step < 8; step++) {
        const int tl = step*2 + tbit;
        uint32_t wd[4];
#pragma unroll
        for (int j = 0; j < 4; j++) {
            const int mloc = mlb + (j & 1)*8;
            const int c0 = tl*16 + kb + (j >> 1)*8;
            float v0 = vals[c0*33 + mloc];
            float v1 = vals[(c0 + 1)*33 + mloc];
            float h0 = __bfloat162float(__float2bfloat16(v0));
            float h1 = __bfloat162float(__float2bfloat16(v1));
            wd[j] = hl ? pack2_bf16(v0 - h0, v1 - h1) : pack2_bf16(h0, h1);
        }
        const int tg = tap*16 + tl;
        const size_t wb = ((size_t)tg*576 + blk576)*512 + (mt*2 + hl)*128 + lane_g*4;
        *reinterpret_cast<uint4*>(g_Af + wb) = make_uint4(wd[0], wd[1], wd[2], wd[3]);
    }
}

// ---------------------------------------------------------------- main GEMM: 3xBF16 m16n8k16
// BM=128 (grid=144), BN=256, BK=32 (2 k16 steps/stage), 512 threads, warp 32x64.
#define STAGE_BYTES 32768            // B: [hi 16KB][lo 16KB] per BK=32 stage
#define SMEM_BYTES  (2*STAGE_BYTES + 256)

__global__ __launch_bounds__(512, 1) void gemm_kernel() {
    extern __shared__ char smem[];
    float* sred = (float*)(smem + 2*STAGE_BYTES);
    const uint32_t sb = smem_u32(smem);
    const int tid = threadIdx.x, lane = tid & 31, wid = tid >> 5;
    const int wm = wid & 3, wn = wid >> 2;
    const int m0 = blockIdx.x * 128;
    const int b = m0 / HW;

    if (tid < 64) sred[tid] = 0.f;

    float acc[2][8][4];
#pragma unroll
    for (int i = 0; i < 2; i++)
#pragma unroll
        for (int j = 0; j < 8; j++)
#pragma unroll
            for (int e = 0; e < 4; e++) acc[i][j][e] = 0.f;

    const size_t ablk = (size_t)blockIdx.x*4 + wm;   // into 576 slots
    uint32_t vah[2][2][4], val[2][2][4];

    auto loadA = [&](int t, int buf) {
        const uint32_t* base = g_Af + ((size_t)t*576 + ablk)*512 + lane*4;
#pragma unroll
        for (int mt = 0; mt < 2; mt++) {
            uint4 h4 = *reinterpret_cast<const uint4*>(base + mt*256);
            uint4 l4 = *reinterpret_cast<const uint4*>(base + mt*256 + 128);
            vah[buf][mt][0] = h4.x; vah[buf][mt][1] = h4.y;
            vah[buf][mt][2] = h4.z; vah[buf][mt][3] = h4.w;
            val[buf][mt][0] = l4.x; val[buf][mt][1] = l4.y;
            val[buf][mt][2] = l4.z; val[buf][mt][3] = l4.w;
        }
    };

    auto issueB = [&](int s, int q) {
        const uint32_t* srcH = g_Wfbh + (size_t)q * 4096;
        const uint32_t* srcL = g_Wfbl + (size_t)q * 4096;
        const uint32_t dH = sb + s*STAGE_BYTES + tid*16;
#pragma unroll
        for (int j = 0; j < 2; j++) {
            CP_ASYNC16(dH + j*8192,         srcH + tid*4 + j*2048);
            CP_ASYNC16(dH + 16384 + j*8192, srcL + tid*4 + j*2048);
        }
    };

    loadA(0, 0);
    issueB(0, 0); CP_COMMIT();

    for (int q = 0; q < NST; q++) {
        CP_WAIT0();
        __syncthreads();
        if (q + 1 < NST) { issueB((q + 1) & 1, q + 1); CP_COMMIT(); }
        const int p = q & 1;

#pragma unroll
        for (int ks = 0; ks < 2; ks++) {
            const int t = q*2 + ks;
            const int buf = t & 1;
            if (t + 1 < NK16) loadA(t + 1, buf ^ 1);

            const char* bb = smem + p*STAGE_BYTES + ks*8192 + lane*8;
#pragma unroll
            for (int nt = 0; nt < 8; nt++) {
                const int ng = wn*8 + nt;
                uint2 bh = *reinterpret_cast<const uint2*>(bb + ng*256);
                uint2 bl = *reinterpret_cast<const uint2*>(bb + ng*256 + 16384);
#pragma unroll
                for (int mt = 0; mt < 2; mt++) {
                    MMA_BF16(acc[mt][nt], vah[buf][mt], bh.x, bh.y);
                    MMA_BF16(acc[mt][nt], vah[buf][mt], bl.x, bl.y);
                    MMA_BF16(acc[mt][nt], val[buf][mt], bh.x, bh.y);
                }
            }
        }
    }

    // Epilogue: write g_O (NHWC) + GN partial sums
    const int mrow = m0 + wm*32 + (lane >> 2);
#pragma unroll
    for (int nt = 0; nt < 8; nt++) {
        const int ng = wn*8 + nt;
        const int n = wn*64 + nt*8 + 2*(lane & 3);
        float s = 0.f, s2 = 0.f;
#pragma unroll
        for (int mt = 0; mt < 2; mt++) {
            float* a4 = acc[mt][nt];
            const int m1 = mrow + mt*16;
            *reinterpret_cast<float2*>(&g_O[(size_t)m1*COUT + n])       = make_float2(a4[0], a4[1]);
            *reinterpret_cast<float2*>(&g_O[(size_t)(m1 + 8)*COUT + n]) = make_float2(a4[2], a4[3]);
            s  += a4[0] + a4[1] + a4[2] + a4[3];
            s2 += a4[0]*a4[0] + a4[1]*a4[1] + a4[2]*a4[2] + a4[3]*a4[3];
        }
#pragma unroll
        for (int o = 16; o > 0; o >>= 1) {
            s  += __shfl_down_sync(0xFFFFFFFFu, s,  o);
            s2 += __shfl_down_sync(0xFFFFFFFFu, s2, o);
        }
        if (lane == 0) {
            atomicAdd(&sred[ng*2 + 0], s);
            atomicAdd(&sred[ng*2 + 1], s2);
        }
    }
    __syncthreads();
    if (tid < 64) atomicAdd(&g_stats[b*64 + tid], sred[tid]);
}

// ---------------------------------------------------------------- GN + ReLU + NHWC->NCHW (smem transpose)
__global__ void norm_kernel(float* __restrict__ out,
                            const float* __restrict__ gamma,
                            const float* __restrict__ beta) {
    __shared__ float tile[32][33];
    const int m0 = blockIdx.x * 32;
    const int o0 = blockIdx.y * 32;
    const int tid = threadIdx.x;            // 256
    const int lane = tid & 31, row = tid >> 5;
    const int b = m0 / HW;

    const int o = o0 + lane;
    const int g = o >> 3;
    float s  = g_stats[(b*NGRP + g)*2 + 0];
    float s2 = g_stats[(b*NGRP + g)*2 + 1];
    float mu  = s  * (1.f / (float)GELEMS);
    float var = s2 * (1.f / (float)GELEMS) - mu*mu;
    float scale = rsqrtf(var + 1e-5f) * gamma[o];
    float shift = beta[o] - mu * scale;

#pragma unroll
    for (int r = 0; r < 4; r++) {
        int ml = r*8 + row;
        float v = g_O[(size_t)(m0 + ml)*COUT + o];
        tile[ml][lane] = fmaxf(fmaf(v, scale, shift), 0.f);
    }
    __syncthreads();
#pragma unroll
    for (int r = 0; r < 4; r++) {
        int ol = r*8 + row;
        int m = m0 + lane;
        out[(size_t)(b*COUT + o0 + ol)*HW + (m - b*HW)] = tile[lane][ol];
    }
}

// ---------------------------------------------------------------- launch
extern "C" void kernel_launch(void* const* d_in, const int* in_sizes, int n_in,
                              void* d_out, int out_size) {
    const float* x     = (const float*)d_in[0];
    const float* off_w = (const float*)d_in[1];
    const float* off_b = (const float*)d_in[2];
    const float* cw    = (const float*)d_in[3];
    const float* gamma = (const float*)d_in[4];
    const float* beta  = (const float*)d_in[5];
    float* out = (float*)d_out;

    cudaFuncSetAttribute(gemm_kernel,
                         cudaFuncAttributeMaxDynamicSharedMemorySize, SMEM_BYTES);

    offset_conv_kernel<<<dim3(WW/32, HH/4, BB), dim3(32, 4)>>>(x, off_w, off_b);
    repack_w_kernel<<<(NK16*32*32*2 + 255)/256, 256>>>(cw);
    gather_kernel<<<dim3(576, KK2), 256>>>(x);
    gemm_kernel<<<NMTILE, 512, SMEM_BYTES>>>();
    norm_kernel<<<dim3(MTOT/32, COUT/32), 256>>>(out, gamma, beta);
}

// round 6
// speedup vs baseline: 1.7075x; 1.7075x over previous
#include <cuda_runtime.h>
#include <cuda_bf16.h>
#include <cstdint>

// Problem constants
#define BB 2
#define CIN 256
#define HH 96
#define WW 96
#define COUT 256
#define KK2 9
#define HW (HH*WW)                 // 9216
#define MTOT (BB*HW)               // 18432
#define KKTOT (KK2*CIN)            // 2304
#define NGRP 32
#define GCH (COUT/NGRP)            // 8
#define GELEMS (GCH*HW)            // 73728
#define NK16 (KKTOT/16)            // 144 k16 steps
#define NST (KKTOT/32)             // 72 BK=32 stages
#define NMTILE (MTOT/128)          // 144 m tiles

// Scratch (static device memory)
__device__ __align__(128) float    g_off[BB*18*HW];             // offsets  [B,18,H,W]
// A fragments: [k16][mtile*4+wm][mt(2)][hi/lo(2)][128 words = lane*4]
__device__ __align__(128) uint32_t g_Af[(size_t)NK16*576*512];
__device__ __align__(128) uint32_t g_Wfbh[NK16*32*32*2];        // B hi frag order [k16][n8][lane][2]
__device__ __align__(128) uint32_t g_Wfbl[NK16*32*32*2];        // B lo
__device__ __align__(128) float    g_O[(size_t)MTOT*COUT];      // GEMM out (NHWC): [M, Cout]
__device__ __align__(128) float    g_stats[NGRP*BB*2];          // per (b,g): sum, sumsq

// ------------------------------------------------------------- helpers
__device__ __forceinline__ uint32_t pack2_bf16(float a, float b) {
    uint16_t ua = __bfloat16_as_ushort(__float2bfloat16(a));
    uint16_t ub = __bfloat16_as_ushort(__float2bfloat16(b));
    return (uint32_t)ua | ((uint32_t)ub << 16);
}

#define CP_ASYNC16(dst, src) \
    asm volatile("cp.async.cg.shared.global [%0], [%1], 16;" \
                 :: "r"((uint32_t)(dst)), "l"(__cvta_generic_to_global(src)) : "memory")
#define CP_COMMIT() asm volatile("cp.async.commit_group;" ::: "memory")
#define CP_WAIT0()  asm volatile("cp.async.wait_group 0;" ::: "memory")

__device__ __forceinline__ uint32_t smem_u32(const void* p) {
    uint32_t a;
    asm("{ .reg .u64 t; cvta.to.shared.u64 t, %1; cvt.u32.u64 %0, t; }"
        : "=r"(a) : "l"(p));
    return a;
}

#define MMA_BF16(acc, a, b0, b1) \
    asm volatile("mma.sync.aligned.m16n8k16.row.col.f32.bf16.bf16.f32 " \
                 "{%0,%1,%2,%3},{%4,%5,%6,%7},{%8,%9},{%0,%1,%2,%3};" \
                 : "+f"((acc)[0]), "+f"((acc)[1]), "+f"((acc)[2]), "+f"((acc)[3]) \
                 : "r"((a)[0]), "r"((a)[1]), "r"((a)[2]), "r"((a)[3]), \
                   "r"(b0), "r"(b1))

// ---------------------------------------------------------------- offset conv
// 512 threads = 4 channel slices x 128 threads (32x4 pixel tile).
// Each slice handles 64 channels with private acc[18]; double-buffered smem;
// one __syncthreads per channel iteration; cross-slice smem reduction at end.
__global__ __launch_bounds__(512) void offset_conv_kernel(const float* __restrict__ x,
                                                          const float* __restrict__ ow,
                                                          const float* __restrict__ ob) {
    __shared__ float xs[4][2][204];                 // 6*34 tile per slice per buf
    __shared__ __align__(16) float ws[4][2][180];   // 9 taps x 18 outs (rows padded to 20)
    __shared__ float red[3][128][18];

    const int tid = threadIdx.x;
    const int slice = tid >> 7;         // 0..3
    const int lt = tid & 127;
    const int tx = lt & 31, ty = lt >> 5;
    const int w0 = blockIdx.x * 32;
    const int h0 = blockIdx.y * 4;
    const int b  = blockIdx.z;
    const int cbase = slice * 64;

    const float* xb = x + (size_t)b * (CIN*HW);

    float acc[18];
#pragma unroll
    for (int j = 0; j < 18; j++) acc[j] = 0.f;

    auto loadTile = [&](int buf, int c) {
        const float* xc = xb + (size_t)c * HW;
#pragma unroll
        for (int i = lt; i < 204; i += 128) {
            int r = i / 34, cc = i % 34;
            int y = h0 - 1 + r, xx = w0 - 1 + cc;
            float v = 0.f;
            if (y >= 0 && y < HH && xx >= 0 && xx < WW) v = xc[y*WW + xx];
            xs[slice][buf][i] = v;
        }
#pragma unroll
        for (int i = lt; i < 162; i += 128) {
            int j = i / 9, t = i % 9;
            ws[slice][buf][t*20 + j] = ow[j*(CIN*9) + c*9 + t];
        }
    };

    loadTile(0, cbase);
    __syncthreads();

    for (int it = 0; it < 64; it++) {
        const int buf = it & 1;
        if (it + 1 < 64) loadTile(buf ^ 1, cbase + it + 1);

        const float* X = xs[slice][buf];
        const float* W = ws[slice][buf];
        float xv[9];
#pragma unroll
        for (int t = 0; t < 9; t++) xv[t] = X[(ty + t/3)*34 + tx + t%3];
#pragma unroll
        for (int t = 0; t < 9; t++) {
            float4 a0 = *(const float4*)&W[t*20 + 0];
            float4 a1 = *(const float4*)&W[t*20 + 4];
            float4 a2 = *(const float4*)&W[t*20 + 8];
            float4 a3 = *(const float4*)&W[t*20 + 12];
            float  a4 = W[t*20 + 16], a5 = W[t*20 + 17];
            float v = xv[t];
            acc[0]  += v*a0.x; acc[1]  += v*a0.y; acc[2]  += v*a0.z; acc[3]  += v*a0.w;
            acc[4]  += v*a1.x; acc[5]  += v*a1.y; acc[6]  += v*a1.z; acc[7]  += v*a1.w;
            acc[8]  += v*a2.x; acc[9]  += v*a2.y; acc[10] += v*a2.z; acc[11] += v*a2.w;
            acc[12] += v*a3.x; acc[13] += v*a3.y; acc[14] += v*a3.z; acc[15] += v*a3.w;
            acc[16] += v*a4;   acc[17] += v*a5;
        }
        __syncthreads();
    }

    if (slice > 0) {
#pragma unroll
        for (int j = 0; j < 18; j++) red[slice - 1][lt][j] = acc[j];
    }
    __syncthreads();
    if (slice == 0) {
        const int h = h0 + ty, w = w0 + tx;
#pragma unroll
        for (int j = 0; j < 18; j++) {
            float v = acc[j] + red[0][lt][j] + red[1][lt][j] + red[2][lt][j];
            g_off[((b*18 + j)*HH + h)*WW + w] = v + ob[j];
        }
    }
}

// ---------------------------------------------------------------- weight repack (+ stats zero)
__global__ void repack_w_kernel(const float* __restrict__ cw) {
    if (blockIdx.x == 0 && threadIdx.x < NGRP*BB*2) g_stats[threadIdx.x] = 0.f;
    int idx = blockIdx.x * 256 + threadIdx.x;   // over NK16*32*32*2 = 294912
    if (idx >= NK16*32*32*2) return;
    int j    = idx & 1;
    int lane = (idx >> 1) & 31;
    int n8   = (idx >> 6) & 31;
    int k16  = idx >> 11;
    int kk0 = k16*16 + j*8 + 2*(lane & 3);
    int n   = n8*8 + (lane >> 2);
    int c0 = kk0 & 255, tap0 = kk0 >> 8;
    int kk1 = kk0 + 1;
    int c1 = kk1 & 255, tap1 = kk1 >> 8;
    float v0 = cw[(n*CIN + c0)*9 + tap0];
    float v1 = cw[(n*CIN + c1)*9 + tap1];
    float h0 = __bfloat162float(__float2bfloat16(v0));
    float h1 = __bfloat162float(__float2bfloat16(v1));
    g_Wfbh[idx] = pack2_bf16(h0, h1);
    g_Wfbl[idx] = pack2_bf16(v0 - h0, v1 - h1);
}

// ---------------------------------------------------------------- gather/im2col -> A fragments (bf16 hi/lo)
__global__ __launch_bounds__(256) void gather_kernel(const float* __restrict__ x) {
    __shared__ float vals[256*33];
    const int tid = threadIdx.x;
    const int ml = tid & 31, cg = tid >> 5;
    const int mchunk = blockIdx.x;       // 0..575
    const int tap = blockIdx.y;          // 0..8
    const int mtile = mchunk >> 2, wm = mchunk & 3;

    const int m = mchunk*32 + ml;
    const int b = m / HW;
    const int rem = m - b*HW;
    const int h = rem / WW, w = rem - h*WW;

    const int off_base = ((b*18 + 2*tap)*HH + h)*WW + w;
    const float dy = g_off[off_base];
    const float dx = g_off[off_base + HW];

    const float sy = (float)(h - 1 + tap/3) + dy;
    const float sx = (float)(w - 1 + tap%3) + dx;
    const float y0f = floorf(sy), x0f = floorf(sx);
    const float fy = sy - y0f, fx = sx - x0f;
    const int y0 = (int)y0f, x0 = (int)x0f;
    const int y1 = y0 + 1,  x1 = x0 + 1;

    const bool vy0 = (y0 >= 0) && (y0 < HH), vy1 = (y1 >= 0) && (y1 < HH);
    const bool vx0 = (x0 >= 0) && (x0 < WW), vx1 = (x1 >= 0) && (x1 < WW);
    const float w00 = (vy0 && vx0) ? (1.f-fy)*(1.f-fx) : 0.f;
    const float w01 = (vy0 && vx1) ? (1.f-fy)*fx       : 0.f;
    const float w10 = (vy1 && vx0) ? fy*(1.f-fx)       : 0.f;
    const float w11 = (vy1 && vx1) ? fy*fx             : 0.f;

    const int cy0 = min(max(y0,0),HH-1), cy1 = min(max(y1,0),HH-1);
    const int cx0 = min(max(x0,0),WW-1), cx1 = min(max(x1,0),WW-1);
    const int i00 = cy0*WW+cx0, i01 = cy0*WW+cx1, i10 = cy1*WW+cx0, i11 = cy1*WW+cx1;

    const float* xb = x + (size_t)b * (CIN*HW);

#pragma unroll 4
    for (int i = 0; i < 32; i++) {
        const int c = i*8 + cg;
        const float* xp = xb + (size_t)c*HW;
        float v = w00*xp[i00] + w01*xp[i01] + w10*xp[i10] + w11*xp[i11];
        vals[c*33 + ml] = v;
    }
    __syncthreads();

    // Phase 2: writer. tid -> (lane_g, mt, hl, tbit)
    const int lane_g = tid & 31;
    const int mt   = (tid >> 5) & 1;
    const int hl   = (tid >> 6) & 1;
    const int tbit = (tid >> 7) & 1;
    const int mlb = mt*16 + (lane_g >> 2);
    const int kb  = 2*(lane_g & 3);
    const size_t blk576 = (size_t)mtile*4 + wm;

#pragma unroll
    for (int step = 0; step < 8; step++) {
        const int tl = step*2 + tbit;
        uint32_t wd[4];
#pragma unroll
        for (int j = 0; j < 4; j++) {
            const int mloc = mlb + (j & 1)*8;
            const int c0 = tl*16 + kb + (j >> 1)*8;
            float v0 = vals[c0*33 + mloc];
            float v1 = vals[(c0 + 1)*33 + mloc];
            float h0 = __bfloat162float(__float2bfloat16(v0));
            float h1 = __bfloat162float(__float2bfloat16(v1));
            wd[j] = hl ? pack2_bf16(v0 - h0, v1 - h1) : pack2_bf16(h0, h1);
        }
        const int tg = tap*16 + tl;
        const size_t wb = ((size_t)tg*576 + blk576)*512 + (mt*2 + hl)*128 + lane_g*4;
        *reinterpret_cast<uint4*>(g_Af + wb) = make_uint4(wd[0], wd[1], wd[2], wd[3]);
    }
}

// ---------------------------------------------------------------- main GEMM: 3xBF16 m16n8k16
#define STAGE_BYTES 32768            // B: [hi 16KB][lo 16KB] per BK=32 stage
#define SMEM_BYTES  (2*STAGE_BYTES + 256)

__global__ __launch_bounds__(512, 1) void gemm_kernel() {
    extern __shared__ char smem[];
    float* sred = (float*)(smem + 2*STAGE_BYTES);
    const uint32_t sb = smem_u32(smem);
    const int tid = threadIdx.x, lane = tid & 31, wid = tid >> 5;
    const int wm = wid & 3, wn = wid >> 2;
    const int m0 = blockIdx.x * 128;
    const int b = m0 / HW;

    if (tid < 64) sred[tid] = 0.f;

    float acc[2][8][4];
#pragma unroll
    for (int i = 0; i < 2; i++)
#pragma unroll
        for (int j = 0; j < 8; j++)
#pragma unroll
            for (int e = 0; e < 4; e++) acc[i][j][e] = 0.f;

    const size_t ablk = (size_t)blockIdx.x*4 + wm;   // into 576 slots
    uint32_t vah[2][2][4], val[2][2][4];

    auto loadA = [&](int t, int buf) {
        const uint32_t* base = g_Af + ((size_t)t*576 + ablk)*512 + lane*4;
#pragma unroll
        for (int mt = 0; mt < 2; mt++) {
            uint4 h4 = *reinterpret_cast<const uint4*>(base + mt*256);
            uint4 l4 = *reinterpret_cast<const uint4*>(base + mt*256 + 128);
            vah[buf][mt][0] = h4.x; vah[buf][mt][1] = h4.y;
            vah[buf][mt][2] = h4.z; vah[buf][mt][3] = h4.w;
            val[buf][mt][0] = l4.x; val[buf][mt][1] = l4.y;
            val[buf][mt][2] = l4.z; val[buf][mt][3] = l4.w;
        }
    };

    auto issueB = [&](int s, int q) {
        const uint32_t* srcH = g_Wfbh + (size_t)q * 4096;
        const uint32_t* srcL = g_Wfbl + (size_t)q * 4096;
        const uint32_t dH = sb + s*STAGE_BYTES + tid*16;
#pragma unroll
        for (int j = 0; j < 2; j++) {
            CP_ASYNC16(dH + j*8192,         srcH + tid*4 + j*2048);
            CP_ASYNC16(dH + 16384 + j*8192, srcL + tid*4 + j*2048);
        }
    };

    loadA(0, 0);
    issueB(0, 0); CP_COMMIT();

    for (int q = 0; q < NST; q++) {
        CP_WAIT0();
        __syncthreads();
        if (q + 1 < NST) { issueB((q + 1) & 1, q + 1); CP_COMMIT(); }
        const int p = q & 1;

#pragma unroll
        for (int ks = 0; ks < 2; ks++) {
            const int t = q*2 + ks;
            const int buf = t & 1;
            if (t + 1 < NK16) loadA(t + 1, buf ^ 1);

            const char* bb = smem + p*STAGE_BYTES + ks*8192 + lane*8;
#pragma unroll
            for (int nt = 0; nt < 8; nt++) {
                const int ng = wn*8 + nt;
                uint2 bh = *reinterpret_cast<const uint2*>(bb + ng*256);
                uint2 bl = *reinterpret_cast<const uint2*>(bb + ng*256 + 16384);
#pragma unroll
                for (int mt = 0; mt < 2; mt++) {
                    MMA_BF16(acc[mt][nt], vah[buf][mt], bh.x, bh.y);
                    MMA_BF16(acc[mt][nt], vah[buf][mt], bl.x, bl.y);
                    MMA_BF16(acc[mt][nt], val[buf][mt], bh.x, bh.y);
                }
            }
        }
    }

    // Epilogue: write g_O (NHWC) + GN partial sums
    const int mrow = m0 + wm*32 + (lane >> 2);
#pragma unroll
    for (int nt = 0; nt < 8; nt++) {
        const int ng = wn*8 + nt;
        const int n = wn*64 + nt*8 + 2*(lane & 3);
        float s = 0.f, s2 = 0.f;
#pragma unroll
        for (int mt = 0; mt < 2; mt++) {
            float* a4 = acc[mt][nt];
            const int m1 = mrow + mt*16;
            *reinterpret_cast<float2*>(&g_O[(size_t)m1*COUT + n])       = make_float2(a4[0], a4[1]);
            *reinterpret_cast<float2*>(&g_O[(size_t)(m1 + 8)*COUT + n]) = make_float2(a4[2], a4[3]);
            s  += a4[0] + a4[1] + a4[2] + a4[3];
            s2 += a4[0]*a4[0] + a4[1]*a4[1] + a4[2]*a4[2] + a4[3]*a4[3];
        }
#pragma unroll
        for (int o = 16; o > 0; o >>= 1) {
            s  += __shfl_down_sync(0xFFFFFFFFu, s,  o);
            s2 += __shfl_down_sync(0xFFFFFFFFu, s2, o);
        }
        if (lane == 0) {
            atomicAdd(&sred[ng*2 + 0], s);
            atomicAdd(&sred[ng*2 + 1], s2);
        }
    }
    __syncthreads();
    if (tid < 64) atomicAdd(&g_stats[b*64 + tid], sred[tid]);
}

// ---------------------------------------------------------------- GN + ReLU + NHWC->NCHW (smem transpose)
__global__ void norm_kernel(float* __restrict__ out,
                            const float* __restrict__ gamma,
                            const float* __restrict__ beta) {
    __shared__ float tile[32][33];
    const int m0 = blockIdx.x * 32;
    const int o0 = blockIdx.y * 32;
    const int tid = threadIdx.x;            // 256
    const int lane = tid & 31, row = tid >> 5;
    const int b = m0 / HW;

    const int o = o0 + lane;
    const int g = o >> 3;
    float s  = g_stats[(b*NGRP + g)*2 + 0];
    float s2 = g_stats[(b*NGRP + g)*2 + 1];
    float mu  = s  * (1.f / (float)GELEMS);
    float var = s2 * (1.f / (float)GELEMS) - mu*mu;
    float scale = rsqrtf(var + 1e-5f) * gamma[o];
    float shift = beta[o] - mu * scale;

#pragma unroll
    for (int r = 0; r < 4; r++) {
        int ml = r*8 + row;
        float v = g_O[(size_t)(m0 + ml)*COUT + o];
        tile[ml][lane] = fmaxf(fmaf(v, scale, shift), 0.f);
    }
    __syncthreads();
#pragma unroll
    for (int r = 0; r < 4; r++) {
        int ol = r*8 + row;
        int m = m0 + lane;
        out[(size_t)(b*COUT + o0 + ol)*HW + (m - b*HW)] = tile[lane][ol];
    }
}

// ---------------------------------------------------------------- launch
extern "C" void kernel_launch(void* const* d_in, const int* in_sizes, int n_in,
                              void* d_out, int out_size) {
    const float* x     = (const float*)d_in[0];
    const float* off_w = (const float*)d_in[1];
    const float* off_b = (const float*)d_in[2];
    const float* cw    = (const float*)d_in[3];
    const float* gamma = (const float*)d_in[4];
    const float* beta  = (const float*)d_in[5];
    float* out = (float*)d_out;

    cudaFuncSetAttribute(gemm_kernel,
                         cudaFuncAttributeMaxDynamicSharedMemorySize, SMEM_BYTES);

    offset_conv_kernel<<<dim3(WW/32, HH/4, BB), 512>>>(x, off_w, off_b);
    repack_w_kernel<<<(NK16*32*32*2 + 255)/256, 256>>>(cw);
    gather_kernel<<<dim3(576, KK2), 256>>>(x);
    gemm_kernel<<<NMTILE, 512, SMEM_BYTES>>>();
    norm_kernel<<<dim3(MTOT/32, COUT/32), 256>>>(out, gamma, beta);
}

// round 7
// speedup vs baseline: 1.7116x; 1.0024x over previous
#include <cuda_runtime.h>
#include <cuda_bf16.h>
#include <cstdint>

// Problem constants
#define BB 2
#define CIN 256
#define HH 96
#define WW 96
#define COUT 256
#define KK2 9
#define HW (HH*WW)                 // 9216
#define MTOT (BB*HW)               // 18432
#define KKTOT (KK2*CIN)            // 2304
#define NGRP 32
#define GCH (COUT/NGRP)            // 8
#define GELEMS (GCH*HW)            // 73728
#define NK16 (KKTOT/16)            // 144 k16 steps
#define NST (KKTOT/32)             // 72 BK=32 stages
#define NMTILE (MTOT/128)          // 144 m tiles

// Scratch (static device memory)
__device__ __align__(128) float    g_off[BB*18*HW];             // offsets  [B,18,H,W]
__device__ __align__(128) uint32_t g_Wfbh[NK16*32*32*2];        // B hi frag order [k16][n8][lane][2]
__device__ __align__(128) uint32_t g_Wfbl[NK16*32*32*2];        // B lo
__device__ __align__(128) float    g_O[(size_t)MTOT*COUT];      // GEMM out (NHWC): [M, Cout]
__device__ __align__(128) float    g_stats[NGRP*BB*2];          // per (b,g): sum, sumsq

// ------------------------------------------------------------- helpers
__device__ __forceinline__ uint32_t pack2_bf16(float a, float b) {
    uint16_t ua = __bfloat16_as_ushort(__float2bfloat16(a));
    uint16_t ub = __bfloat16_as_ushort(__float2bfloat16(b));
    return (uint32_t)ua | ((uint32_t)ub << 16);
}

#define CP_ASYNC16(dst, src) \
    asm volatile("cp.async.cg.shared.global [%0], [%1], 16;" \
                 :: "r"((uint32_t)(dst)), "l"(__cvta_generic_to_global(src)) : "memory")
#define CP_COMMIT() asm volatile("cp.async.commit_group;" ::: "memory")
#define CP_WAIT0()  asm volatile("cp.async.wait_group 0;" ::: "memory")

__device__ __forceinline__ uint32_t smem_u32(const void* p) {
    uint32_t a;
    asm("{ .reg .u64 t; cvta.to.shared.u64 t, %1; cvt.u32.u64 %0, t; }"
        : "=r"(a) : "l"(p));
    return a;
}

#define MMA_BF16(acc, a, b0, b1) \
    asm volatile("mma.sync.aligned.m16n8k16.row.col.f32.bf16.bf16.f32 " \
                 "{%0,%1,%2,%3},{%4,%5,%6,%7},{%8,%9},{%0,%1,%2,%3};" \
                 : "+f"((acc)[0]), "+f"((acc)[1]), "+f"((acc)[2]), "+f"((acc)[3]) \
                 : "r"((a)[0]), "r"((a)[1]), "r"((a)[2]), "r"((a)[3]), \
                   "r"(b0), "r"(b1))

// ---------------------------------------------------------------- offset conv
__global__ __launch_bounds__(512) void offset_conv_kernel(const float* __restrict__ x,
                                                          const float* __restrict__ ow,
                                                          const float* __restrict__ ob) {
    __shared__ float xs[4][2][204];
    __shared__ __align__(16) float ws[4][2][180];
    __shared__ float red[3][128][18];

    const int tid = threadIdx.x;
    const int slice = tid >> 7;
    const int lt = tid & 127;
    const int tx = lt & 31, ty = lt >> 5;
    const int w0 = blockIdx.x * 32;
    const int h0 = blockIdx.y * 4;
    const int b  = blockIdx.z;
    const int cbase = slice * 64;

    const float* xb = x + (size_t)b * (CIN*HW);

    float acc[18];
#pragma unroll
    for (int j = 0; j < 18; j++) acc[j] = 0.f;

    auto loadTile = [&](int buf, int c) {
        const float* xc = xb + (size_t)c * HW;
#pragma unroll
        for (int i = lt; i < 204; i += 128) {
            int r = i / 34, cc = i % 34;
            int y = h0 - 1 + r, xx = w0 - 1 + cc;
            float v = 0.f;
            if (y >= 0 && y < HH && xx >= 0 && xx < WW) v = xc[y*WW + xx];
            xs[slice][buf][i] = v;
        }
#pragma unroll
        for (int i = lt; i < 162; i += 128) {
            int j = i / 9, t = i % 9;
            ws[slice][buf][t*20 + j] = ow[j*(CIN*9) + c*9 + t];
        }
    };

    loadTile(0, cbase);
    __syncthreads();

    for (int it = 0; it < 64; it++) {
        const int buf = it & 1;
        if (it + 1 < 64) loadTile(buf ^ 1, cbase + it + 1);

        const float* X = xs[slice][buf];
        const float* W = ws[slice][buf];
        float xv[9];
#pragma unroll
        for (int t = 0; t < 9; t++) xv[t] = X[(ty + t/3)*34 + tx + t%3];
#pragma unroll
        for (int t = 0; t < 9; t++) {
            float4 a0 = *(const float4*)&W[t*20 + 0];
            float4 a1 = *(const float4*)&W[t*20 + 4];
            float4 a2 = *(const float4*)&W[t*20 + 8];
            float4 a3 = *(const float4*)&W[t*20 + 12];
            float  a4 = W[t*20 + 16], a5 = W[t*20 + 17];
            float v = xv[t];
            acc[0]  += v*a0.x; acc[1]  += v*a0.y; acc[2]  += v*a0.z; acc[3]  += v*a0.w;
            acc[4]  += v*a1.x; acc[5]  += v*a1.y; acc[6]  += v*a1.z; acc[7]  += v*a1.w;
            acc[8]  += v*a2.x; acc[9]  += v*a2.y; acc[10] += v*a2.z; acc[11] += v*a2.w;
            acc[12] += v*a3.x; acc[13] += v*a3.y; acc[14] += v*a3.z; acc[15] += v*a3.w;
            acc[16] += v*a4;   acc[17] += v*a5;
        }
        __syncthreads();
    }

    if (slice > 0) {
#pragma unroll
        for (int j = 0; j < 18; j++) red[slice - 1][lt][j] = acc[j];
    }
    __syncthreads();
    if (slice == 0) {
        const int h = h0 + ty, w = w0 + tx;
#pragma unroll
        for (int j = 0; j < 18; j++) {
            float v = acc[j] + red[0][lt][j] + red[1][lt][j] + red[2][lt][j];
            g_off[((b*18 + j)*HH + h)*WW + w] = v + ob[j];
        }
    }
}

// ---------------------------------------------------------------- weight repack (+ stats zero)
__global__ void repack_w_kernel(const float* __restrict__ cw) {
    if (blockIdx.x == 0 && threadIdx.x < NGRP*BB*2) g_stats[threadIdx.x] = 0.f;
    int idx = blockIdx.x * 256 + threadIdx.x;   // over NK16*32*32*2 = 294912
    if (idx >= NK16*32*32*2) return;
    int j    = idx & 1;
    int lane = (idx >> 1) & 31;
    int n8   = (idx >> 6) & 31;
    int k16  = idx >> 11;
    int kk0 = k16*16 + j*8 + 2*(lane & 3);
    int n   = n8*8 + (lane >> 2);
    int c0 = kk0 & 255, tap0 = kk0 >> 8;
    int kk1 = kk0 + 1;
    int c1 = kk1 & 255, tap1 = kk1 >> 8;
    float v0 = cw[(n*CIN + c0)*9 + tap0];
    float v1 = cw[(n*CIN + c1)*9 + tap1];
    float h0 = __bfloat162float(__float2bfloat16(v0));
    float h1 = __bfloat162float(__float2bfloat16(v1));
    g_Wfbh[idx] = pack2_bf16(h0, h1);
    g_Wfbl[idx] = pack2_bf16(v0 - h0, v1 - h1);
}

// ---------------------------------------------------------------- fused gather + 3xBF16 GEMM + GN partials
// BM=128 (grid=144), BN=256, BK=32, 512 threads (16 warps: wm=wid&3, wn=wid>>2).
// Producer role: every thread gathers/packs A fragments for iter q+1 into smem
// (double-buffered); consumer role: MMAs from smem A + smem B.
// smem: [0,64K) B 2 stages; [64K,96K) A 2 stages (per stage: [ks][wm][plane][512B]); [96K,+256) sred
#define B_STAGE 32768
#define A_BASE  65536
#define A_STAGE 16384
#define SRED_OFF 98304
#define SMEM_BYTES (98304 + 256)

__global__ __launch_bounds__(512, 1) void gemm_kernel(const float* __restrict__ x) {
    extern __shared__ char smem[];
    float* sred = (float*)(smem + SRED_OFF);
    const uint32_t sb = smem_u32(smem);
    const int tid = threadIdx.x, lane = tid & 31, wid = tid >> 5;
    const int wm = wid & 3, wn = wid >> 2;
    const int m0 = blockIdx.x * 128;
    const int b = m0 / HW;
    const float* xb = x + (size_t)b * (CIN*HW);

    if (tid < 64) sred[tid] = 0.f;

    float acc[2][8][4];
#pragma unroll
    for (int i = 0; i < 2; i++)
#pragma unroll
        for (int j = 0; j < 8; j++)
#pragma unroll
            for (int e = 0; e < 4; e++) acc[i][j][e] = 0.f;

    // ---- producer identity: (p_wm, p_mt, p_jh) x lane ----
    const int p_wm = wid & 3;
    const int p_mt = (wid >> 2) & 1;
    const int p_jh = (wid >> 3) & 1;
    const int p_m0 = m0 + p_wm*32 + p_mt*16 + (lane >> 2);
    const int p_cl = 2*(lane & 3) + p_jh*8;

    int   gi[2][4];
    float gw[2][4];

    auto tapParams = [&](int tap) {
#pragma unroll
        for (int px = 0; px < 2; px++) {
            const int mm = p_m0 + px*8;
            const int rem = mm - b*HW;
            const int h = rem / WW, w = rem - h*WW;
            const int obidx = ((b*18 + 2*tap)*HH + h)*WW + w;
            const float dy = g_off[obidx];
            const float dx = g_off[obidx + HW];
            const float sy = (float)(h - 1 + tap/3) + dy;
            const float sx = (float)(w - 1 + tap%3) + dx;
            const float y0f = floorf(sy), x0f = floorf(sx);
            const float fy = sy - y0f, fx = sx - x0f;
            const int y0 = (int)y0f, x0 = (int)x0f;
            const int y1 = y0 + 1,  x1 = x0 + 1;
            const bool vy0 = (y0 >= 0) && (y0 < HH), vy1 = (y1 >= 0) && (y1 < HH);
            const bool vx0 = (x0 >= 0) && (x0 < WW), vx1 = (x1 >= 0) && (x1 < WW);
            gw[px][0] = (vy0 && vx0) ? (1.f-fy)*(1.f-fx) : 0.f;
            gw[px][1] = (vy0 && vx1) ? (1.f-fy)*fx       : 0.f;
            gw[px][2] = (vy1 && vx0) ? fy*(1.f-fx)       : 0.f;
            gw[px][3] = (vy1 && vx1) ? fy*fx             : 0.f;
            const int cy0 = min(max(y0,0),HH-1), cy1 = min(max(y1,0),HH-1);
            const int cx0 = min(max(x0,0),WW-1), cx1 = min(max(x1,0),WW-1);
            gi[px][0] = cy0*WW+cx0; gi[px][1] = cy0*WW+cx1;
            gi[px][2] = cy1*WW+cx0; gi[px][3] = cy1*WW+cx1;
        }
    };

    auto produce = [&](int t, int s, int ks) {
        const int tl = t & 15;
        const int c0 = tl*16 + p_cl;
        const float* xa = xb + (size_t)c0*HW;
        const float* xc = xa + HW;
        uint32_t hw[2], lw[2];
#pragma unroll
        for (int px = 0; px < 2; px++) {
            float v0 = gw[px][0]*xa[gi[px][0]] + gw[px][1]*xa[gi[px][1]]
                     + gw[px][2]*xa[gi[px][2]] + gw[px][3]*xa[gi[px][3]];
            float v1 = gw[px][0]*xc[gi[px][0]] + gw[px][1]*xc[gi[px][1]]
                     + gw[px][2]*xc[gi[px][2]] + gw[px][3]*xc[gi[px][3]];
            float h0 = __bfloat162float(__float2bfloat16(v0));
            float h1 = __bfloat162float(__float2bfloat16(v1));
            hw[px] = pack2_bf16(h0, h1);
            lw[px] = pack2_bf16(v0 - h0, v1 - h1);
        }
        char* ap = smem + A_BASE + s*A_STAGE + ks*8192 + p_wm*2048 + p_mt*1024 + lane*16 + p_jh*8;
        *reinterpret_cast<uint2*>(ap)       = make_uint2(hw[0], hw[1]);
        *reinterpret_cast<uint2*>(ap + 512) = make_uint2(lw[0], lw[1]);
    };

    auto issueB = [&](int s, int q) {
        const uint32_t* srcH = g_Wfbh + (size_t)q * 4096;
        const uint32_t* srcL = g_Wfbl + (size_t)q * 4096;
        const uint32_t dH = sb + s*B_STAGE + tid*16;
#pragma unroll
        for (int j = 0; j < 2; j++) {
            CP_ASYNC16(dH + j*8192,         srcH + tid*4 + j*2048);
            CP_ASYNC16(dH + 16384 + j*8192, srcL + tid*4 + j*2048);
        }
    };

    // prologue
    tapParams(0);
    produce(0, 0, 0);
    produce(1, 0, 1);
    issueB(0, 0); CP_COMMIT();

    for (int q = 0; q < NST; q++) {
        CP_WAIT0();
        __syncthreads();
        const bool more = (q + 1 < NST);
        if (more) { issueB((q + 1) & 1, q + 1); CP_COMMIT(); }
        if (more && (((q + 1) & 7) == 0)) tapParams((q + 1) >> 3);
        const int p = q & 1;

#pragma unroll
        for (int ks = 0; ks < 2; ks++) {
            if (more) produce(2*(q + 1) + ks, (q + 1) & 1, ks);

            // consume: A frags from smem
            const char* ab = smem + A_BASE + p*A_STAGE + ks*8192 + wm*2048 + lane*16;
            uint32_t ah[2][4], al[2][4];
#pragma unroll
            for (int mt = 0; mt < 2; mt++) {
                uint4 h4 = *reinterpret_cast<const uint4*>(ab + mt*1024);
                uint4 l4 = *reinterpret_cast<const uint4*>(ab + mt*1024 + 512);
                ah[mt][0] = h4.x; ah[mt][1] = h4.y; ah[mt][2] = h4.z; ah[mt][3] = h4.w;
                al[mt][0] = l4.x; al[mt][1] = l4.y; al[mt][2] = l4.z; al[mt][3] = l4.w;
            }

            const char* bb = smem + p*B_STAGE + ks*8192 + lane*8;
#pragma unroll
            for (int nt = 0; nt < 8; nt++) {
                const int ng = wn*8 + nt;
                uint2 bh = *reinterpret_cast<const uint2*>(bb + ng*256);
                uint2 bl = *reinterpret_cast<const uint2*>(bb + ng*256 + 16384);
#pragma unroll
                for (int mt = 0; mt < 2; mt++) {
                    MMA_BF16(acc[mt][nt], ah[mt], bh.x, bh.y);
                    MMA_BF16(acc[mt][nt], ah[mt], bl.x, bl.y);
                    MMA_BF16(acc[mt][nt], al[mt], bh.x, bh.y);
                }
            }
        }
    }

    // Epilogue: write g_O (NHWC) + GN partial sums
    const int mrow = m0 + wm*32 + (lane >> 2);
#pragma unroll
    for (int nt = 0; nt < 8; nt++) {
        const int ng = wn*8 + nt;
        const int n = wn*64 + nt*8 + 2*(lane & 3);
        float s = 0.f, s2 = 0.f;
#pragma unroll
        for (int mt = 0; mt < 2; mt++) {
            float* a4 = acc[mt][nt];
            const int m1 = mrow + mt*16;
            *reinterpret_cast<float2*>(&g_O[(size_t)m1*COUT + n])       = make_float2(a4[0], a4[1]);
            *reinterpret_cast<float2*>(&g_O[(size_t)(m1 + 8)*COUT + n]) = make_float2(a4[2], a4[3]);
            s  += a4[0] + a4[1] + a4[2] + a4[3];
            s2 += a4[0]*a4[0] + a4[1]*a4[1] + a4[2]*a4[2] + a4[3]*a4[3];
        }
#pragma unroll
        for (int o = 16; o > 0; o >>= 1) {
            s  += __shfl_down_sync(0xFFFFFFFFu, s,  o);
            s2 += __shfl_down_sync(0xFFFFFFFFu, s2, o);
        }
        if (lane == 0) {
            atomicAdd(&sred[ng*2 + 0], s);
            atomicAdd(&sred[ng*2 + 1], s2);
        }
    }
    __syncthreads();
    if (tid < 64) atomicAdd(&g_stats[b*64 + tid], sred[tid]);
}

// ---------------------------------------------------------------- GN + ReLU + NHWC->NCHW (smem transpose)
__global__ void norm_kernel(float* __restrict__ out,
                            const float* __restrict__ gamma,
                            const float* __restrict__ beta) {
    __shared__ float tile[32][33];
    const int m0 = blockIdx.x * 32;
    const int o0 = blockIdx.y * 32;
    const int tid = threadIdx.x;            // 256
    const int lane = tid & 31, row = tid >> 5;
    const int b = m0 / HW;

    const int o = o0 + lane;
    const int g = o >> 3;
    float s  = g_stats[(b*NGRP + g)*2 + 0];
    float s2 = g_stats[(b*NGRP + g)*2 + 1];
    float mu  = s  * (1.f / (float)GELEMS);
    float var = s2 * (1.f / (float)GELEMS) - mu*mu;
    float scale = rsqrtf(var + 1e-5f) * gamma[o];
    float shift = beta[o] - mu * scale;

#pragma unroll
    for (int r = 0; r < 4; r++) {
        int ml = r*8 + row;
        float v = g_O[(size_t)(m0 + ml)*COUT + o];
        tile[ml][lane] = fmaxf(fmaf(v, scale, shift), 0.f);
    }
    __syncthreads();
#pragma unroll
    for (int r = 0; r < 4; r++) {
        int ol = r*8 + row;
        int m = m0 + lane;
        out[(size_t)(b*COUT + o0 + ol)*HW + (m - b*HW)] = tile[lane][ol];
    }
}

// ---------------------------------------------------------------- launch
extern "C" void kernel_launch(void* const* d_in, const int* in_sizes, int n_in,
                              void* d_out, int out_size) {
    const float* x     = (const float*)d_in[0];
    const float* off_w = (const float*)d_in[1];
    const float* off_b = (const float*)d_in[2];
    const float* cw    = (const float*)d_in[3];
    const float* gamma = (const float*)d_in[4];
    const float* beta  = (const float*)d_in[5];
    float* out = (float*)d_out;

    cudaFuncSetAttribute(gemm_kernel,
                         cudaFuncAttributeMaxDynamicSharedMemorySize, SMEM_BYTES);

    offset_conv_kernel<<<dim3(WW/32, HH/4, BB), 512>>>(x, off_w, off_b);
    repack_w_kernel<<<(NK16*32*32*2 + 255)/256, 256>>>(cw);
    gemm_kernel<<<NMTILE, 512, SMEM_BYTES>>>(x);
    norm_kernel<<<dim3(MTOT/32, COUT/32), 256>>>(out, gamma, beta);
}

// round 8
// speedup vs baseline: 2.3528x; 1.3746x over previous
#include <cuda_runtime.h>
#include <cuda_bf16.h>
#include <cstdint>

// Problem constants
#define BB 2
#define CIN 256
#define HH 96
#define WW 96
#define COUT 256
#define KK2 9
#define HW (HH*WW)                 // 9216
#define MTOT (BB*HW)               // 18432
#define KKTOT (KK2*CIN)            // 2304
#define NGRP 32
#define GCH (COUT/NGRP)            // 8
#define GELEMS (GCH*HW)            // 73728
#define NK16 (KKTOT/16)            // 144 k16 steps
#define NST (KKTOT/32)             // 72 BK=32 stages

// Scratch (static device memory)
__device__ __align__(128) float    g_off[BB*18*HW];             // offsets  [B,18,H,W]
__device__ __align__(128) float    g_xt[(size_t)MTOT*CIN];      // x in NHWC: [b*HW+pix][c]
__device__ __align__(128) uint32_t g_Wfbh[NK16*32*32*2];        // B hi frag order [k16][n8][lane][2]
__device__ __align__(128) uint32_t g_Wfbl[NK16*32*32*2];        // B lo
__device__ __align__(128) float    g_O[(size_t)MTOT*COUT];      // GEMM out (NHWC): [M, Cout]
__device__ __align__(128) float    g_stats[NGRP*BB*2];          // per (b,g): sum, sumsq

// ------------------------------------------------------------- helpers
__device__ __forceinline__ uint32_t pack2_bf16(float a, float b) {
    uint16_t ua = __bfloat16_as_ushort(__float2bfloat16(a));
    uint16_t ub = __bfloat16_as_ushort(__float2bfloat16(b));
    return (uint32_t)ua | ((uint32_t)ub << 16);
}

#define CP_ASYNC16(dst, src) \
    asm volatile("cp.async.cg.shared.global [%0], [%1], 16;" \
                 :: "r"((uint32_t)(dst)), "l"(__cvta_generic_to_global(src)) : "memory")
#define CP_COMMIT() asm volatile("cp.async.commit_group;" ::: "memory")
#define CP_WAIT0()  asm volatile("cp.async.wait_group 0;" ::: "memory")

__device__ __forceinline__ uint32_t smem_u32(const void* p) {
    uint32_t a;
    asm("{ .reg .u64 t; cvta.to.shared.u64 t, %1; cvt.u32.u64 %0, t; }"
        : "=r"(a) : "l"(p));
    return a;
}

#define MMA_BF16(acc, a, b0, b1) \
    asm volatile("mma.sync.aligned.m16n8k16.row.col.f32.bf16.bf16.f32 " \
                 "{%0,%1,%2,%3},{%4,%5,%6,%7},{%8,%9},{%0,%1,%2,%3};" \
                 : "+f"((acc)[0]), "+f"((acc)[1]), "+f"((acc)[2]), "+f"((acc)[3]) \
                 : "r"((a)[0]), "r"((a)[1]), "r"((a)[2]), "r"((a)[3]), \
                   "r"(b0), "r"(b1))

// ---------------------------------------------------------------- offset conv
__global__ __launch_bounds__(512) void offset_conv_kernel(const float* __restrict__ x,
                                                          const float* __restrict__ ow,
                                                          const float* __restrict__ ob) {
    __shared__ float xs[4][2][204];
    __shared__ __align__(16) float ws[4][2][180];
    __shared__ float red[3][128][18];

    const int tid = threadIdx.x;
    const int slice = tid >> 7;
    const int lt = tid & 127;
    const int tx = lt & 31, ty = lt >> 5;
    const int w0 = blockIdx.x * 32;
    const int h0 = blockIdx.y * 4;
    const int b  = blockIdx.z;
    const int cbase = slice * 64;

    const float* xb = x + (size_t)b * (CIN*HW);

    float acc[18];
#pragma unroll
    for (int j = 0; j < 18; j++) acc[j] = 0.f;

    auto loadTile = [&](int buf, int c) {
        const float* xc = xb + (size_t)c * HW;
#pragma unroll
        for (int i = lt; i < 204; i += 128) {
            int r = i / 34, cc = i % 34;
            int y = h0 - 1 + r, xx = w0 - 1 + cc;
            float v = 0.f;
            if (y >= 0 && y < HH && xx >= 0 && xx < WW) v = xc[y*WW + xx];
            xs[slice][buf][i] = v;
        }
#pragma unroll
        for (int i = lt; i < 162; i += 128) {
            int j = i / 9, t = i % 9;
            ws[slice][buf][t*20 + j] = ow[j*(CIN*9) + c*9 + t];
        }
    };

    loadTile(0, cbase);
    __syncthreads();

    for (int it = 0; it < 64; it++) {
        const int buf = it & 1;
        if (it + 1 < 64) loadTile(buf ^ 1, cbase + it + 1);

        const float* X = xs[slice][buf];
        const float* W = ws[slice][buf];
        float xv[9];
#pragma unroll
        for (int t = 0; t < 9; t++) xv[t] = X[(ty + t/3)*34 + tx + t%3];
#pragma unroll
        for (int t = 0; t < 9; t++) {
            float4 a0 = *(const float4*)&W[t*20 + 0];
            float4 a1 = *(const float4*)&W[t*20 + 4];
            float4 a2 = *(const float4*)&W[t*20 + 8];
            float4 a3 = *(const float4*)&W[t*20 + 12];
            float  a4 = W[t*20 + 16], a5 = W[t*20 + 17];
            float v = xv[t];
            acc[0]  += v*a0.x; acc[1]  += v*a0.y; acc[2]  += v*a0.z; acc[3]  += v*a0.w;
            acc[4]  += v*a1.x; acc[5]  += v*a1.y; acc[6]  += v*a1.z; acc[7]  += v*a1.w;
            acc[8]  += v*a2.x; acc[9]  += v*a2.y; acc[10] += v*a2.z; acc[11] += v*a2.w;
            acc[12] += v*a3.x; acc[13] += v*a3.y; acc[14] += v*a3.z; acc[15] += v*a3.w;
            acc[16] += v*a4;   acc[17] += v*a5;
        }
        __syncthreads();
    }

    if (slice > 0) {
#pragma unroll
        for (int j = 0; j < 18; j++) red[slice - 1][lt][j] = acc[j];
    }
    __syncthreads();
    if (slice == 0) {
        const int h = h0 + ty, w = w0 + tx;
#pragma unroll
        for (int j = 0; j < 18; j++) {
            float v = acc[j] + red[0][lt][j] + red[1][lt][j] + red[2][lt][j];
            g_off[((b*18 + j)*HH + h)*WW + w] = v + ob[j];
        }
    }
}

// ---------------------------------------------------------------- NCHW -> NHWC transpose of x
__global__ __launch_bounds__(256) void transpose_kernel(const float* __restrict__ x) {
    __shared__ float tile[32][33];
    const int m0 = blockIdx.x * 32;      // 576
    const int c0 = blockIdx.y * 32;      // 8
    const int tid = threadIdx.x;
    const int lane = tid & 31, row = tid >> 5;
    const int b = m0 / HW;
    const int pix0 = m0 - b*HW;

#pragma unroll
    for (int r = 0; r < 4; r++) {
        int cl = row + r*8;
        tile[cl][lane] = x[(size_t)(b*CIN + c0 + cl)*HW + pix0 + lane];
    }
    __syncthreads();
#pragma unroll
    for (int r = 0; r < 4; r++) {
        int pl = row + r*8;
        g_xt[(size_t)(m0 + pl)*CIN + c0 + lane] = tile[lane][pl];
    }
}

// ---------------------------------------------------------------- weight repack (+ stats zero)
__global__ void repack_w_kernel(const float* __restrict__ cw) {
    if (blockIdx.x == 0 && threadIdx.x < NGRP*BB*2) g_stats[threadIdx.x] = 0.f;
    int idx = blockIdx.x * 256 + threadIdx.x;   // over NK16*32*32*2 = 294912
    if (idx >= NK16*32*32*2) return;
    int j    = idx & 1;
    int lane = (idx >> 1) & 31;
    int n8   = (idx >> 6) & 31;
    int k16  = idx >> 11;
    int kk0 = k16*16 + j*8 + 2*(lane & 3);
    int n   = n8*8 + (lane >> 2);
    int c0 = kk0 & 255, tap0 = kk0 >> 8;
    int kk1 = kk0 + 1;
    int c1 = kk1 & 255, tap1 = kk1 >> 8;
    float v0 = cw[(n*CIN + c0)*9 + tap0];
    float v1 = cw[(n*CIN + c1)*9 + tap1];
    float h0 = __bfloat162float(__float2bfloat16(v0));
    float h1 = __bfloat162float(__float2bfloat16(v1));
    g_Wfbh[idx] = pack2_bf16(h0, h1);
    g_Wfbl[idx] = pack2_bf16(v0 - h0, v1 - h1);
}

// ---------------------------------------------------------------- fused gather + 3xBF16 GEMM + GN partials
// BM=64 (grid=288, 2 CTAs/SM), BN=256, BK=32, 256 threads (8 warps: wm=wid&1, wn=wid>>1).
// Producer: each thread owns one m (tid>>2) and 8 channels ((tid&3)*8) per stage;
// NHWC float4 corner loads; LDG->STS split around MMA bursts for latency hiding.
// smem: [0,64K) B 2 stages; [64K,80K) A 2 stages; [80K,+256) sred
#define B_STAGE 32768
#define A_BASE  65536
#define A_STG   8192
#define SRED_OFF 81920
#define SMEM_BYTES (81920 + 256)

__global__ __launch_bounds__(256, 2) void gemm_kernel() {
    extern __shared__ char smem[];
    float* sred = (float*)(smem + SRED_OFF);
    const uint32_t sb = smem_u32(smem);
    const int tid = threadIdx.x, lane = tid & 31, wid = tid >> 5;
    const int wm = wid & 1, wn = wid >> 1;
    const int m0 = blockIdx.x * 64;
    const int b = m0 / HW;

    if (tid < 64) sred[tid] = 0.f;

    float acc[2][8][4];
#pragma unroll
    for (int i = 0; i < 2; i++)
#pragma unroll
        for (int j = 0; j < 8; j++)
#pragma unroll
            for (int e = 0; e < 4; e++) acc[i][j][e] = 0.f;

    // ---- producer identity ----
    const int m_l  = tid >> 2;                 // 0..63
    const int cgrp = tid & 3;                  // channel group (8 ch)
    const int p_wm = (m_l >> 5) & 1;
    const int p_mt = (m_l >> 4) & 1;
    const int p_px = (m_l >> 3) & 1;
    const int p_row = m_l & 7;
    const int p_ks = cgrp >> 1, p_jh = cgrp & 1;
    const int mm = m0 + m_l;
    const int rem = mm - b*HW;
    const int h = rem / WW, w = rem - h*WW;

    uint32_t gib[4];       // absolute NHWC row base (m_global * 256)
    float    gw[4];

    auto tapParams = [&](int tap) {
        const int obidx = ((b*18 + 2*tap)*HH + h)*WW + w;
        const float dy = g_off[obidx];
        const float dx = g_off[obidx + HW];
        const float sy = (float)(h - 1 + tap/3) + dy;
        const float sx = (float)(w - 1 + tap%3) + dx;
        const float y0f = floorf(sy), x0f = floorf(sx);
        const float fy = sy - y0f, fx = sx - x0f;
        const int y0 = (int)y0f, x0 = (int)x0f;
        const int y1 = y0 + 1,  x1 = x0 + 1;
        const bool vy0 = (y0 >= 0) && (y0 < HH), vy1 = (y1 >= 0) && (y1 < HH);
        const bool vx0 = (x0 >= 0) && (x0 < WW), vx1 = (x1 >= 0) && (x1 < WW);
        gw[0] = (vy0 && vx0) ? (1.f-fy)*(1.f-fx) : 0.f;
        gw[1] = (vy0 && vx1) ? (1.f-fy)*fx       : 0.f;
        gw[2] = (vy1 && vx0) ? fy*(1.f-fx)       : 0.f;
        gw[3] = (vy1 && vx1) ? fy*fx             : 0.f;
        const int cy0 = min(max(y0,0),HH-1), cy1 = min(max(y1,0),HH-1);
        const int cx0 = min(max(x0,0),WW-1), cx1 = min(max(x1,0),WW-1);
        gib[0] = (uint32_t)(b*HW + cy0*WW+cx0) * CIN;
        gib[1] = (uint32_t)(b*HW + cy0*WW+cx1) * CIN;
        gib[2] = (uint32_t)(b*HW + cy1*WW+cx0) * CIN;
        gib[3] = (uint32_t)(b*HW + cy1*WW+cx1) * CIN;
    };

    float4 cv[4];
    auto loadG = [&](int g, int q1) {
        const int cg = ((q1 & 7) << 5) + cgrp*8 + g*4;
#pragma unroll
        for (int c = 0; c < 4; c++)
            cv[c] = *reinterpret_cast<const float4*>(g_xt + (size_t)gib[c] + cg);
    };

    auto stsG = [&](int g, int s) {
        float v0 = gw[0]*cv[0].x + gw[1]*cv[1].x + gw[2]*cv[2].x + gw[3]*cv[3].x;
        float v1 = gw[0]*cv[0].y + gw[1]*cv[1].y + gw[2]*cv[2].y + gw[3]*cv[3].y;
        float v2 = gw[0]*cv[0].z + gw[1]*cv[1].z + gw[2]*cv[2].z + gw[3]*cv[3].z;
        float v3 = gw[0]*cv[0].w + gw[1]*cv[1].w + gw[2]*cv[2].w + gw[3]*cv[3].w;
        float h0 = __bfloat162float(__float2bfloat16(v0));
        float h1 = __bfloat162float(__float2bfloat16(v1));
        float h2 = __bfloat162float(__float2bfloat16(v2));
        float h3 = __bfloat162float(__float2bfloat16(v3));
        uint32_t hw0 = pack2_bf16(h0, h1),      hw1 = pack2_bf16(h2, h3);
        uint32_t lw0 = pack2_bf16(v0-h0, v1-h1), lw1 = pack2_bf16(v2-h2, v3-h3);
        char* base = smem + A_BASE + s*A_STG + p_ks*4096 + p_wm*2048 + p_mt*1024;
        const int woff = p_jh*8 + p_px*4;
        const int sl0 = p_row*4 + ((g*2)     ^ (p_row & 3));
        const int sl1 = p_row*4 + ((g*2 + 1) ^ (p_row & 3));
        *(uint32_t*)(base + sl0*16 + woff)       = hw0;
        *(uint32_t*)(base + sl1*16 + woff)       = hw1;
        *(uint32_t*)(base + 512 + sl0*16 + woff) = lw0;
        *(uint32_t*)(base + 512 + sl1*16 + woff) = lw1;
    };

    auto issueB = [&](int s, int q) {
        const uint32_t* srcH = g_Wfbh + (size_t)q * 4096;
        const uint32_t* srcL = g_Wfbl + (size_t)q * 4096;
        const uint32_t dH = sb + s*B_STAGE + tid*16;
#pragma unroll
        for (int j = 0; j < 4; j++) {
            CP_ASYNC16(dH + j*4096,         srcH + tid*4 + j*1024);
            CP_ASYNC16(dH + 16384 + j*4096, srcL + tid*4 + j*1024);
        }
    };

    const int lane_sw = lane ^ ((lane >> 2) & 3);

    auto mmaStep = [&](int p, int ks) {
        const char* ab = smem + A_BASE + p*A_STG + ks*4096 + wm*2048 + lane_sw*16;
        uint32_t ah[2][4], al[2][4];
#pragma unroll
        for (int mt = 0; mt < 2; mt++) {
            uint4 h4 = *reinterpret_cast<const uint4*>(ab + mt*1024);
            uint4 l4 = *reinterpret_cast<const uint4*>(ab + mt*1024 + 512);
            ah[mt][0] = h4.x; ah[mt][1] = h4.y; ah[mt][2] = h4.z; ah[mt][3] = h4.w;
            al[mt][0] = l4.x; al[mt][1] = l4.y; al[mt][2] = l4.z; al[mt][3] = l4.w;
        }
        const char* bb = smem + p*B_STAGE + ks*8192 + lane*8;
#pragma unroll
        for (int nt = 0; nt < 8; nt++) {
            const int ng = wn*8 + nt;
            uint2 bh = *reinterpret_cast<const uint2*>(bb + ng*256);
            uint2 bl = *reinterpret_cast<const uint2*>(bb + ng*256 + 16384);
#pragma unroll
            for (int mt = 0; mt < 2; mt++) {
                MMA_BF16(acc[mt][nt], ah[mt], bh.x, bh.y);
                MMA_BF16(acc[mt][nt], ah[mt], bl.x, bl.y);
                MMA_BF16(acc[mt][nt], al[mt], bh.x, bh.y);
            }
        }
    };

    // prologue: produce stage 0, start B stage 0
    tapParams(0);
    loadG(0, 0); stsG(0, 0);
    loadG(1, 0); stsG(1, 0);
    issueB(0, 0); CP_COMMIT();

    for (int q = 0; q < NST; q++) {
        CP_WAIT0();
        __syncthreads();
        const bool more = (q + 1 < NST);
        if (more) { issueB((q + 1) & 1, q + 1); CP_COMMIT(); }
        if (more && (((q + 1) & 7) == 0)) tapParams((q + 1) >> 3);
        const int p = q & 1;

        if (more) loadG(0, q + 1);
        mmaStep(p, 0);
        if (more) { stsG(0, (q + 1) & 1); loadG(1, q + 1); }
        mmaStep(p, 1);
        if (more) stsG(1, (q + 1) & 1);
    }

    // Epilogue: write g_O (NHWC) + GN partial sums
    const int mrow = m0 + wm*32 + (lane >> 2);
#pragma unroll
    for (int nt = 0; nt < 8; nt++) {
        const int ng = wn*8 + nt;
        const int n = wn*64 + nt*8 + 2*(lane & 3);
        float s = 0.f, s2 = 0.f;
#pragma unroll
        for (int mt = 0; mt < 2; mt++) {
            float* a4 = acc[mt][nt];
            const int m1 = mrow + mt*16;
            *reinterpret_cast<float2*>(&g_O[(size_t)m1*COUT + n])       = make_float2(a4[0], a4[1]);
            *reinterpret_cast<float2*>(&g_O[(size_t)(m1 + 8)*COUT + n]) = make_float2(a4[2], a4[3]);
            s  += a4[0] + a4[1] + a4[2] + a4[3];
            s2 += a4[0]*a4[0] + a4[1]*a4[1] + a4[2]*a4[2] + a4[3]*a4[3];
        }
#pragma unroll
        for (int o = 16; o > 0; o >>= 1) {
            s  += __shfl_down_sync(0xFFFFFFFFu, s,  o);
            s2 += __shfl_down_sync(0xFFFFFFFFu, s2, o);
        }
        if (lane == 0) {
            atomicAdd(&sred[ng*2 + 0], s);
            atomicAdd(&sred[ng*2 + 1], s2);
        }
    }
    __syncthreads();
    if (tid < 64) atomicAdd(&g_stats[b*64 + tid], sred[tid]);
}

// ---------------------------------------------------------------- GN + ReLU + NHWC->NCHW (smem transpose)
__global__ void norm_kernel(float* __restrict__ out,
                            const float* __restrict__ gamma,
                            const float* __restrict__ beta) {
    __shared__ float tile[32][33];
    const int m0 = blockIdx.x * 32;
    const int o0 = blockIdx.y * 32;
    const int tid = threadIdx.x;            // 256
    const int lane = tid & 31, row = tid >> 5;
    const int b = m0 / HW;

    const int o = o0 + lane;
    const int g = o >> 3;
    float s  = g_stats[(b*NGRP + g)*2 + 0];
    float s2 = g_stats[(b*NGRP + g)*2 + 1];
    float mu  = s  * (1.f / (float)GELEMS);
    float var = s2 * (1.f / (float)GELEMS) - mu*mu;
    float scale = rsqrtf(var + 1e-5f) * gamma[o];
    float shift = beta[o] - mu * scale;

#pragma unroll
    for (int r = 0; r < 4; r++) {
        int ml = r*8 + row;
        float v = g_O[(size_t)(m0 + ml)*COUT + o];
        tile[ml][lane] = fmaxf(fmaf(v, scale, shift), 0.f);
    }
    __syncthreads();
#pragma unroll
    for (int r = 0; r < 4; r++) {
        int ol = r*8 + row;
        int m = m0 + lane;
        out[(size_t)(b*COUT + o0 + ol)*HW + (m - b*HW)] = tile[lane][ol];
    }
}

// ---------------------------------------------------------------- launch
extern "C" void kernel_launch(void* const* d_in, const int* in_sizes, int n_in,
                              void* d_out, int out_size) {
    const float* x     = (const float*)d_in[0];
    const float* off_w = (const float*)d_in[1];
    const float* off_b = (const float*)d_in[2];
    const float* cw    = (const float*)d_in[3];
    const float* gamma = (const float*)d_in[4];
    const float* beta  = (const float*)d_in[5];
    float* out = (float*)d_out;

    cudaFuncSetAttribute(gemm_kernel,
                         cudaFuncAttributeMaxDynamicSharedMemorySize, SMEM_BYTES);

    offset_conv_kernel<<<dim3(WW/32, HH/4, BB), 512>>>(x, off_w, off_b);
    transpose_kernel<<<dim3(MTOT/32, CIN/32), 256>>>(x);
    repack_w_kernel<<<(NK16*32*32*2 + 255)/256, 256>>>(cw);
    gemm_kernel<<<MTOT/64, 256, SMEM_BYTES>>>();
    norm_kernel<<<dim3(MTOT/32, COUT/32), 256>>>(out, gamma, beta);
}

// round 9
// speedup vs baseline: 2.5608x; 1.0884x over previous
#include <cuda_runtime.h>
#include <cuda_bf16.h>
#include <cstdint>

// Problem constants
#define BB 2
#define CIN 256
#define HH 96
#define WW 96
#define COUT 256
#define KK2 9
#define HW (HH*WW)                 // 9216
#define MTOT (BB*HW)               // 18432
#define KKTOT (KK2*CIN)            // 2304
#define NGRP 32
#define GCH (COUT/NGRP)            // 8
#define GELEMS (GCH*HW)            // 73728
#define NK16 (KKTOT/16)            // 144 k16 steps
#define NST (KKTOT/32)             // 72 BK=32 stages

// Scratch (static device memory)
__device__ __align__(128) float    g_off[BB*18*HW];             // offsets  [B,18,H,W]
__device__ __align__(128) float    g_xt[(size_t)MTOT*CIN];      // x in NHWC: [b*HW+pix][c]
__device__ __align__(128) uint32_t g_Wfbh[NK16*16*32*4];        // B hi frag order [k16][ngpair][lane][4]
__device__ __align__(128) uint32_t g_Wfbl[NK16*16*32*4];        // B lo
__device__ __align__(128) uint32_t g_OWfh[NK16*3*32*2];         // offset-conv B hi [k16][ng][lane][2]
__device__ __align__(128) uint32_t g_OWfl[NK16*3*32*2];         // offset-conv B lo
__device__ __align__(128) float    g_O[(size_t)MTOT*COUT];      // GEMM out (NHWC): [M, Cout]
__device__ __align__(128) float    g_stats[NGRP*BB*2];          // per (b,g): sum, sumsq

// ------------------------------------------------------------- helpers
__device__ __forceinline__ uint32_t pack2_bf16(float a, float b) {
    uint16_t ua = __bfloat16_as_ushort(__float2bfloat16(a));
    uint16_t ub = __bfloat16_as_ushort(__float2bfloat16(b));
    return (uint32_t)ua | ((uint32_t)ub << 16);
}

#define CP_ASYNC16(dst, src) \
    asm volatile("cp.async.cg.shared.global [%0], [%1], 16;" \
                 :: "r"((uint32_t)(dst)), "l"(__cvta_generic_to_global(src)) : "memory")
#define CP_COMMIT() asm volatile("cp.async.commit_group;" ::: "memory")
#define CP_WAIT0()  asm volatile("cp.async.wait_group 0;" ::: "memory")

__device__ __forceinline__ uint32_t smem_u32(const void* p) {
    uint32_t a;
    asm("{ .reg .u64 t; cvta.to.shared.u64 t, %1; cvt.u32.u64 %0, t; }"
        : "=r"(a) : "l"(p));
    return a;
}

#define MMA_BF16(acc, a, b0, b1) \
    asm volatile("mma.sync.aligned.m16n8k16.row.col.f32.bf16.bf16.f32 " \
                 "{%0,%1,%2,%3},{%4,%5,%6,%7},{%8,%9},{%0,%1,%2,%3};" \
                 : "+f"((acc)[0]), "+f"((acc)[1]), "+f"((acc)[2]), "+f"((acc)[3]) \
                 : "r"((a)[0]), "r"((a)[1]), "r"((a)[2]), "r"((a)[3]), \
                   "r"(b0), "r"(b1))

// ---------------------------------------------------------------- NCHW -> NHWC transpose of x
__global__ __launch_bounds__(256) void transpose_kernel(const float* __restrict__ x) {
    __shared__ float tile[32][33];
    const int m0 = blockIdx.x * 32;      // 576
    const int c0 = blockIdx.y * 32;      // 8
    const int tid = threadIdx.x;
    const int lane = tid & 31, row = tid >> 5;
    const int b = m0 / HW;
    const int pix0 = m0 - b*HW;

#pragma unroll
    for (int r = 0; r < 4; r++) {
        int cl = row + r*8;
        tile[cl][lane] = x[(size_t)(b*CIN + c0 + cl)*HW + pix0 + lane];
    }
    __syncthreads();
#pragma unroll
    for (int r = 0; r < 4; r++) {
        int pl = row + r*8;
        g_xt[(size_t)(m0 + pl)*CIN + c0 + lane] = tile[lane][pl];
    }
}

// ---------------------------------------------------------------- main weight repack (+ stats zero)
// layout: [k16][ngpair(16)][lane][4 words]; word w: ng = pr*2+(w>>1), j = w&1
__global__ void repack_w_kernel(const float* __restrict__ cw) {
    if (blockIdx.x == 0 && threadIdx.x < NGRP*BB*2) g_stats[threadIdx.x] = 0.f;
    int idx = blockIdx.x * 256 + threadIdx.x;   // over NK16*16*32*4 = 294912
    if (idx >= NK16*16*32*4) return;
    int w4   = idx & 3;
    int lane = (idx >> 2) & 31;
    int pr   = (idx >> 7) & 15;
    int k16  = idx >> 11;
    int ng = pr*2 + (w4 >> 1);
    int j  = w4 & 1;
    int kk0 = k16*16 + j*8 + 2*(lane & 3);
    int n   = ng*8 + (lane >> 2);
    int c0 = kk0 & 255, tap0 = kk0 >> 8;
    int kk1 = kk0 + 1;
    int c1 = kk1 & 255, tap1 = kk1 >> 8;
    float v0 = cw[(n*CIN + c0)*9 + tap0];
    float v1 = cw[(n*CIN + c1)*9 + tap1];
    float h0 = __bfloat162float(__float2bfloat16(v0));
    float h1 = __bfloat162float(__float2bfloat16(v1));
    g_Wfbh[idx] = pack2_bf16(h0, h1);
    g_Wfbl[idx] = pack2_bf16(v0 - h0, v1 - h1);
}

// ---------------------------------------------------------------- offset weight repack
// [k16][ng(3)][lane][2]; n = ng*8 + lane>>2 (pad n>=18 with 0)
__global__ void repack_ow_kernel(const float* __restrict__ ow) {
    int idx = blockIdx.x * 256 + threadIdx.x;   // over NK16*3*32*2 = 27648
    if (idx >= NK16*3*32*2) return;
    int j    = idx & 1;
    int t    = idx >> 1;
    int lane = t & 31; t >>= 5;
    int ng   = t % 3;
    int k16  = t / 3;
    int kk0 = k16*16 + j*8 + 2*(lane & 3);
    int n   = ng*8 + (lane >> 2);
    int c0 = kk0 & 255, tap0 = kk0 >> 8;
    int kk1 = kk0 + 1;
    int c1 = kk1 & 255, tap1 = kk1 >> 8;
    float v0 = (n < 18) ? ow[(n*CIN + c0)*9 + tap0] : 0.f;
    float v1 = (n < 18) ? ow[(n*CIN + c1)*9 + tap1] : 0.f;
    float h0 = __bfloat162float(__float2bfloat16(v0));
    float h1 = __bfloat162float(__float2bfloat16(v1));
    g_OWfh[idx] = pack2_bf16(h0, h1);
    g_OWfl[idx] = pack2_bf16(v0 - h0, v1 - h1);
}

// ---------------------------------------------------------------- offset conv as 3xBF16 GEMM
// M=18432 (BM=128, grid=144), N=24 (18 real), K=2304. 256 threads = 8 warps,
// warp tile 16 x 24 (acc[3][4]). Producer: thread pair per row, plain shifted
// window loads from g_xt (zero-padded).
__global__ __launch_bounds__(256, 1) void offset_gemm_kernel(const float* __restrict__ ob) {
    __shared__ __align__(16) char asmb[2][16384];   // A: [ks][wm16(8)][1KB: 512 hi + 512 lo]
    __shared__ __align__(16) char bsmb[2][3072];    // B: [hi 1536][lo 1536]
    const int tid = threadIdx.x, lane = tid & 31, wid = tid >> 5;
    const int m0 = blockIdx.x * 128;
    const int b = m0 / HW;

    float acc[3][4];
#pragma unroll
    for (int i = 0; i < 3; i++)
#pragma unroll
        for (int e = 0; e < 4; e++) acc[i][e] = 0.f;

    // producer identity
    const int m_l  = tid >> 1;          // 0..127
    const int half = tid & 1;           // ks, 16 channels
    const int p_wm = m_l >> 4;          // 0..7
    const int p_px = (m_l >> 3) & 1;
    const int p_row = m_l & 7;
    const int mm = m0 + m_l;
    const int rem = mm - b*HW;
    const int h = rem / WW, w = rem - h*WW;

    int64_t gptr = 0;
    bool valid = false;
    auto tapParams = [&](int tap) {
        const int py = h - 1 + tap/3, pxx = w - 1 + tap%3;
        valid = (py >= 0) && (py < HH) && (pxx >= 0) && (pxx < WW);
        gptr = (int64_t)(b*HW + py*WW + pxx) * CIN;
    };

    float4 cv[4];
    auto loadG = [&](int q1) {
        const int c0s = ((q1 & 7) << 5) + half*16;
        if (valid) {
#pragma unroll
            for (int f = 0; f < 4; f++)
                cv[f] = *reinterpret_cast<const float4*>(g_xt + gptr + c0s + f*4);
        } else {
#pragma unroll
            for (int f = 0; f < 4; f++) cv[f] = make_float4(0.f, 0.f, 0.f, 0.f);
        }
    };

    auto stsG = [&](int s) {
        char* base = asmb[s] + half*8192 + p_wm*1024;
#pragma unroll
        for (int f = 0; f < 4; f++) {
            const int jh = f >> 1;
            const int pA = (f & 1)*2, pB = pA + 1;
            float v0 = cv[f].x, v1 = cv[f].y, v2 = cv[f].z, v3 = cv[f].w;
            float h0 = __bfloat162float(__float2bfloat16(v0));
            float h1 = __bfloat162float(__float2bfloat16(v1));
            float h2 = __bfloat162float(__float2bfloat16(v2));
            float h3 = __bfloat162float(__float2bfloat16(v3));
            const int woff = jh*8 + p_px*4;
            const int sl0 = p_row*4 + (pA ^ (p_row & 3));
            const int sl1 = p_row*4 + (pB ^ (p_row & 3));
            *(uint32_t*)(base + sl0*16 + woff)       = pack2_bf16(h0, h1);
            *(uint32_t*)(base + sl1*16 + woff)       = pack2_bf16(h2, h3);
            *(uint32_t*)(base + 512 + sl0*16 + woff) = pack2_bf16(v0-h0, v1-h1);
            *(uint32_t*)(base + 512 + sl1*16 + woff) = pack2_bf16(v2-h2, v3-h3);
        }
    };

    const uint32_t bsb = smem_u32(bsmb);
    auto issueB = [&](int s, int q) {
        if (tid < 96) {
            CP_ASYNC16(bsb + s*3072 + tid*16,        g_OWfh + (size_t)q*384 + tid*4);
            CP_ASYNC16(bsb + s*3072 + 1536 + tid*16, g_OWfl + (size_t)q*384 + tid*4);
        }
    };

    const int lane_sw = lane ^ ((lane >> 2) & 3);

    auto mmaStep = [&](int p, int ks) {
        const char* ab = asmb[p] + ks*8192 + wid*1024 + lane_sw*16;
        uint4 h4 = *reinterpret_cast<const uint4*>(ab);
        uint4 l4 = *reinterpret_cast<const uint4*>(ab + 512);
        uint32_t ah[4] = {h4.x, h4.y, h4.z, h4.w};
        uint32_t al[4] = {l4.x, l4.y, l4.z, l4.w};
        const char* bb = bsmb[p] + ks*768 + lane*8;
#pragma unroll
        for (int ng = 0; ng < 3; ng++) {
            uint2 bh = *reinterpret_cast<const uint2*>(bb + ng*256);
            uint2 bl = *reinterpret_cast<const uint2*>(bb + ng*256 + 1536);
            MMA_BF16(acc[ng], ah, bh.x, bh.y);
            MMA_BF16(acc[ng], ah, bl.x, bl.y);
            MMA_BF16(acc[ng], al, bh.x, bh.y);
        }
    };

    // prologue
    tapParams(0);
    loadG(0);
    stsG(0);
    issueB(0, 0); CP_COMMIT();

    for (int q = 0; q < NST; q++) {
        const bool more = (q + 1 < NST);
        if (more && (((q + 1) & 7) == 0)) tapParams((q + 1) >> 3);
        if (more) loadG(q + 1);
        CP_WAIT0();
        __syncthreads();
        if (more) { issueB((q + 1) & 1, q + 1); CP_COMMIT(); }
        const int p = q & 1;
        mmaStep(p, 0);
        mmaStep(p, 1);
        if (more) stsG((q + 1) & 1);
    }

    // epilogue: offsets + bias (n < 18)
    const int mrow = m0 + wid*16 + (lane >> 2);
#pragma unroll
    for (int ng = 0; ng < 3; ng++) {
#pragma unroll
        for (int e = 0; e < 2; e++) {
            const int n = ng*8 + 2*(lane & 3) + e;
            if (n < 18) {
                const float bias = ob[n];
#pragma unroll
                for (int px = 0; px < 2; px++) {
                    const int m = mrow + px*8;
                    const int pr = m - b*HW;
                    g_off[(b*18 + n)*HW + pr] = acc[ng][px*2 + e] + bias;
                }
            }
        }
    }
}

// ---------------------------------------------------------------- fused gather + 3xBF16 GEMM + GN partials
// BM=64 (grid=288, 2 CTAs/SM), BN=256, BK=32, 256 threads (8 warps: wm=wid&1, wn=wid>>1).
#define B_STAGE 32768
#define A_BASE  65536
#define A_STG   8192
#define SRED_OFF 81920
#define SMEM_BYTES (81920 + 256)

__global__ __launch_bounds__(256, 2) void gemm_kernel() {
    extern __shared__ char smem[];
    float* sred = (float*)(smem + SRED_OFF);
    const uint32_t sb = smem_u32(smem);
    const int tid = threadIdx.x, lane = tid & 31, wid = tid >> 5;
    const int wm = wid & 1, wn = wid >> 1;
    const int m0 = blockIdx.x * 64;
    const int b = m0 / HW;

    if (tid < 64) sred[tid] = 0.f;

    float acc[2][8][4];
#pragma unroll
    for (int i = 0; i < 2; i++)
#pragma unroll
        for (int j = 0; j < 8; j++)
#pragma unroll
            for (int e = 0; e < 4; e++) acc[i][j][e] = 0.f;

    // ---- producer identity ----
    const int m_l  = tid >> 2;                 // 0..63
    const int cgrp = tid & 3;                  // channel group (8 ch)
    const int p_wm = (m_l >> 5) & 1;
    const int p_mt = (m_l >> 4) & 1;
    const int p_px = (m_l >> 3) & 1;
    const int p_row = m_l & 7;
    const int p_ks = cgrp >> 1, p_jh = cgrp & 1;
    const int mm = m0 + m_l;
    const int rem = mm - b*HW;
    const int h = rem / WW, w = rem - h*WW;

    uint32_t gib[4];
    float    gw[4];

    auto tapParams = [&](int tap) {
        const int obidx = ((b*18 + 2*tap)*HH + h)*WW + w;
        const float dy = g_off[obidx];
        const float dx = g_off[obidx + HW];
        const float sy = (float)(h - 1 + tap/3) + dy;
        const float sx = (float)(w - 1 + tap%3) + dx;
        const float y0f = floorf(sy), x0f = floorf(sx);
        const float fy = sy - y0f, fx = sx - x0f;
        const int y0 = (int)y0f, x0 = (int)x0f;
        const int y1 = y0 + 1,  x1 = x0 + 1;
        const bool vy0 = (y0 >= 0) && (y0 < HH), vy1 = (y1 >= 0) && (y1 < HH);
        const bool vx0 = (x0 >= 0) && (x0 < WW), vx1 = (x1 >= 0) && (x1 < WW);
        gw[0] = (vy0 && vx0) ? (1.f-fy)*(1.f-fx) : 0.f;
        gw[1] = (vy0 && vx1) ? (1.f-fy)*fx       : 0.f;
        gw[2] = (vy1 && vx0) ? fy*(1.f-fx)       : 0.f;
        gw[3] = (vy1 && vx1) ? fy*fx             : 0.f;
        const int cy0 = min(max(y0,0),HH-1), cy1 = min(max(y1,0),HH-1);
        const int cx0 = min(max(x0,0),WW-1), cx1 = min(max(x1,0),WW-1);
        gib[0] = (uint32_t)(b*HW + cy0*WW+cx0) * CIN;
        gib[1] = (uint32_t)(b*HW + cy0*WW+cx1) * CIN;
        gib[2] = (uint32_t)(b*HW + cy1*WW+cx0) * CIN;
        gib[3] = (uint32_t)(b*HW + cy1*WW+cx1) * CIN;
    };

    float4 cv[4];
    auto loadG = [&](int g, int q1) {
        const int cg = ((q1 & 7) << 5) + cgrp*8 + g*4;
#pragma unroll
        for (int c = 0; c < 4; c++)
            cv[c] = *reinterpret_cast<const float4*>(g_xt + (size_t)gib[c] + cg);
    };

    auto stsG = [&](int g, int s) {
        float v0 = gw[0]*cv[0].x + gw[1]*cv[1].x + gw[2]*cv[2].x + gw[3]*cv[3].x;
        float v1 = gw[0]*cv[0].y + gw[1]*cv[1].y + gw[2]*cv[2].y + gw[3]*cv[3].y;
        float v2 = gw[0]*cv[0].z + gw[1]*cv[1].z + gw[2]*cv[2].z + gw[3]*cv[3].z;
        float v3 = gw[0]*cv[0].w + gw[1]*cv[1].w + gw[2]*cv[2].w + gw[3]*cv[3].w;
        float h0 = __bfloat162float(__float2bfloat16(v0));
        float h1 = __bfloat162float(__float2bfloat16(v1));
        float h2 = __bfloat162float(__float2bfloat16(v2));
        float h3 = __bfloat162float(__float2bfloat16(v3));
        uint32_t hw0 = pack2_bf16(h0, h1),      hw1 = pack2_bf16(h2, h3);
        uint32_t lw0 = pack2_bf16(v0-h0, v1-h1), lw1 = pack2_bf16(v2-h2, v3-h3);
        char* base = smem + A_BASE + s*A_STG + p_ks*4096 + p_wm*2048 + p_mt*1024;
        const int woff = p_jh*8 + p_px*4;
        const int sl0 = p_row*4 + ((g*2)     ^ (p_row & 3));
        const int sl1 = p_row*4 + ((g*2 + 1) ^ (p_row & 3));
        *(uint32_t*)(base + sl0*16 + woff)       = hw0;
        *(uint32_t*)(base + sl1*16 + woff)       = hw1;
        *(uint32_t*)(base + 512 + sl0*16 + woff) = lw0;
        *(uint32_t*)(base + 512 + sl1*16 + woff) = lw1;
    };

    auto issueB = [&](int s, int q) {
        const uint32_t* srcH = g_Wfbh + (size_t)q * 4096;
        const uint32_t* srcL = g_Wfbl + (size_t)q * 4096;
        const uint32_t dH = sb + s*B_STAGE + tid*16;
#pragma unroll
        for (int j = 0; j < 4; j++) {
            CP_ASYNC16(dH + j*4096,         srcH + tid*4 + j*1024);
            CP_ASYNC16(dH + 16384 + j*4096, srcL + tid*4 + j*1024);
        }
    };

    const int lane_sw = lane ^ ((lane >> 2) & 3);

    auto mmaStep = [&](int p, int ks) {
        const char* ab = smem + A_BASE + p*A_STG + ks*4096 + wm*2048 + lane_sw*16;
        uint32_t ah[2][4], al[2][4];
#pragma unroll
        for (int mt = 0; mt < 2; mt++) {
            uint4 h4 = *reinterpret_cast<const uint4*>(ab + mt*1024);
            uint4 l4 = *reinterpret_cast<const uint4*>(ab + mt*1024 + 512);
            ah[mt][0] = h4.x; ah[mt][1] = h4.y; ah[mt][2] = h4.z; ah[mt][3] = h4.w;
            al[mt][0] = l4.x; al[mt][1] = l4.y; al[mt][2] = l4.z; al[mt][3] = l4.w;
        }
        const char* bb = smem + p*B_STAGE + ks*8192 + lane*16;
#pragma unroll
        for (int ntp = 0; ntp < 4; ntp++) {
            uint4 bh = *reinterpret_cast<const uint4*>(bb + (wn*4 + ntp)*512);
            uint4 bl = *reinterpret_cast<const uint4*>(bb + (wn*4 + ntp)*512 + 16384);
#pragma unroll
            for (int mt = 0; mt < 2; mt++) {
                MMA_BF16(acc[mt][ntp*2],     ah[mt], bh.x, bh.y);
                MMA_BF16(acc[mt][ntp*2],     ah[mt], bl.x, bl.y);
                MMA_BF16(acc[mt][ntp*2],     al[mt], bh.x, bh.y);
                MMA_BF16(acc[mt][ntp*2 + 1], ah[mt], bh.z, bh.w);
                MMA_BF16(acc[mt][ntp*2 + 1], ah[mt], bl.z, bl.w);
                MMA_BF16(acc[mt][ntp*2 + 1], al[mt], bh.z, bh.w);
            }
        }
    };

    // prologue
    tapParams(0);
    loadG(0, 0); stsG(0, 0);
    loadG(1, 0); stsG(1, 0);
    issueB(0, 0); CP_COMMIT();

    for (int q = 0; q < NST; q++) {
        CP_WAIT0();
        __syncthreads();
        const bool more = (q + 1 < NST);
        if (more) { issueB((q + 1) & 1, q + 1); CP_COMMIT(); }
        if (more && (((q + 1) & 7) == 0)) tapParams((q + 1) >> 3);
        const int p = q & 1;

        if (more) loadG(0, q + 1);
        mmaStep(p, 0);
        if (more) { stsG(0, (q + 1) & 1); loadG(1, q + 1); }
        mmaStep(p, 1);
        if (more) stsG(1, (q + 1) & 1);
    }

    // Epilogue: write g_O (NHWC) + GN partial sums
    const int mrow = m0 + wm*32 + (lane >> 2);
#pragma unroll
    for (int nt = 0; nt < 8; nt++) {
        const int ng = wn*8 + nt;
        const int n = wn*64 + nt*8 + 2*(lane & 3);
        float s = 0.f, s2 = 0.f;
#pragma unroll
        for (int mt = 0; mt < 2; mt++) {
            float* a4 = acc[mt][nt];
            const int m1 = mrow + mt*16;
            *reinterpret_cast<float2*>(&g_O[(size_t)m1*COUT + n])       = make_float2(a4[0], a4[1]);
            *reinterpret_cast<float2*>(&g_O[(size_t)(m1 + 8)*COUT + n]) = make_float2(a4[2], a4[3]);
            s  += a4[0] + a4[1] + a4[2] + a4[3];
            s2 += a4[0]*a4[0] + a4[1]*a4[1] + a4[2]*a4[2] + a4[3]*a4[3];
        }
#pragma unroll
        for (int o = 16; o > 0; o >>= 1) {
            s  += __shfl_down_sync(0xFFFFFFFFu, s,  o);
            s2 += __shfl_down_sync(0xFFFFFFFFu, s2, o);
        }
        if (lane == 0) {
            atomicAdd(&sred[ng*2 + 0], s);
            atomicAdd(&sred[ng*2 + 1], s2);
        }
    }
    __syncthreads();
    if (tid < 64) atomicAdd(&g_stats[b*64 + tid], sred[tid]);
}

// ---------------------------------------------------------------- GN + ReLU + NHWC->NCHW (smem transpose)
__global__ void norm_kernel(float* __restrict__ out,
                            const float* __restrict__ gamma,
                            const float* __restrict__ beta) {
    __shared__ float tile[32][33];
    const int m0 = blockIdx.x * 32;
    const int o0 = blockIdx.y * 32;
    const int tid = threadIdx.x;            // 256
    const int lane = tid & 31, row = tid >> 5;
    const int b = m0 / HW;

    const int o = o0 + lane;
    const int g = o >> 3;
    float s  = g_stats[(b*NGRP + g)*2 + 0];
    float s2 = g_stats[(b*NGRP + g)*2 + 1];
    float mu  = s  * (1.f / (float)GELEMS);
    float var = s2 * (1.f / (float)GELEMS) - mu*mu;
    float scale = rsqrtf(var + 1e-5f) * gamma[o];
    float shift = beta[o] - mu * scale;

#pragma unroll
    for (int r = 0; r < 4; r++) {
        int ml = r*8 + row;
        float v = g_O[(size_t)(m0 + ml)*COUT + o];
        tile[ml][lane] = fmaxf(fmaf(v, scale, shift), 0.f);
    }
    __syncthreads();
#pragma unroll
    for (int r = 0; r < 4; r++) {
        int ol = r*8 + row;
        int m = m0 + lane;
        out[(size_t)(b*COUT + o0 + ol)*HW + (m - b*HW)] = tile[lane][ol];
    }
}

// ---------------------------------------------------------------- launch
extern "C" void kernel_launch(void* const* d_in, const int* in_sizes, int n_in,
                              void* d_out, int out_size) {
    const float* x     = (const float*)d_in[0];
    const float* off_w = (const float*)d_in[1];
    const float* off_b = (const float*)d_in[2];
    const float* cw    = (const float*)d_in[3];
    const float* gamma = (const float*)d_in[4];
    const float* beta  = (const float*)d_in[5];
    float* out = (float*)d_out;

    cudaFuncSetAttribute(gemm_kernel,
                         cudaFuncAttributeMaxDynamicSharedMemorySize, SMEM_BYTES);

    transpose_kernel<<<dim3(MTOT/32, CIN/32), 256>>>(x);
    repack_w_kernel<<<(NK16*16*32*4 + 255)/256, 256>>>(cw);
    repack_ow_kernel<<<(NK16*3*32*2 + 255)/256, 256>>>(off_w);
    offset_gemm_kernel<<<MTOT/128, 256>>>(off_b);
    gemm_kernel<<<MTOT/64, 256, SMEM_BYTES>>>();
    norm_kernel<<<dim3(MTOT/32, COUT/32), 256>>>(out, gamma, beta);
}

// round 10
// speedup vs baseline: 2.6409x; 1.0313x over previous
#include <cuda_runtime.h>
#include <cuda_bf16.h>
#include <cstdint>

// Problem constants
#define BB 2
#define CIN 256
#define HH 96
#define WW 96
#define COUT 256
#define KK2 9
#define HW (HH*WW)                 // 9216
#define MTOT (BB*HW)               // 18432
#define KKTOT (KK2*CIN)            // 2304
#define NGRP 32
#define GCH (COUT/NGRP)            // 8
#define GELEMS (GCH*HW)            // 73728
#define NK16 (KKTOT/16)            // 144 k16 steps
#define NST (KKTOT/32)             // 72 BK=32 stages

// Scratch (static device memory)
__device__ __align__(128) float    g_off[BB*18*HW];             // offsets  [B,18,H,W]
__device__ __align__(128) float    g_xt[(size_t)MTOT*CIN];      // x in NHWC: [b*HW+pix][c]
__device__ __align__(128) uint32_t g_Wfbh[NK16*16*32*4];        // B hi frag order [k16][ngpair][lane][4]
__device__ __align__(128) uint32_t g_Wfbl[NK16*16*32*4];        // B lo
__device__ __align__(128) uint32_t g_OWfh[NK16*4*32*2];         // offset-conv B hi [k16][ng4][lane][2]
__device__ __align__(128) uint32_t g_OWfl[NK16*4*32*2];         // offset-conv B lo
__device__ __align__(128) float    g_O[(size_t)MTOT*COUT];      // GEMM out (NHWC): [M, Cout]
__device__ __align__(128) float    g_stats[NGRP*BB*2];          // per (b,g): sum, sumsq

// ------------------------------------------------------------- helpers
__device__ __forceinline__ uint32_t pack2_bf16(float a, float b) {
    uint16_t ua = __bfloat16_as_ushort(__float2bfloat16(a));
    uint16_t ub = __bfloat16_as_ushort(__float2bfloat16(b));
    return (uint32_t)ua | ((uint32_t)ub << 16);
}

#define CP_ASYNC16(dst, src) \
    asm volatile("cp.async.cg.shared.global [%0], [%1], 16;" \
                 :: "r"((uint32_t)(dst)), "l"(__cvta_generic_to_global(src)) : "memory")
#define CP_COMMIT() asm volatile("cp.async.commit_group;" ::: "memory")
#define CP_WAIT0()  asm volatile("cp.async.wait_group 0;" ::: "memory")

__device__ __forceinline__ uint32_t smem_u32(const void* p) {
    uint32_t a;
    asm("{ .reg .u64 t; cvta.to.shared.u64 t, %1; cvt.u32.u64 %0, t; }"
        : "=r"(a) : "l"(p));
    return a;
}

#define MMA_BF16(acc, a, b0, b1) \
    asm volatile("mma.sync.aligned.m16n8k16.row.col.f32.bf16.bf16.f32 " \
                 "{%0,%1,%2,%3},{%4,%5,%6,%7},{%8,%9},{%0,%1,%2,%3};" \
                 : "+f"((acc)[0]), "+f"((acc)[1]), "+f"((acc)[2]), "+f"((acc)[3]) \
                 : "r"((a)[0]), "r"((a)[1]), "r"((a)[2]), "r"((a)[3]), \
                   "r"(b0), "r"(b1))

// ---------------------------------------------------------------- NCHW -> NHWC transpose of x
__global__ __launch_bounds__(256) void transpose_kernel(const float* __restrict__ x) {
    __shared__ float tile[32][33];
    const int m0 = blockIdx.x * 32;      // 576
    const int c0 = blockIdx.y * 32;      // 8
    const int tid = threadIdx.x;
    const int lane = tid & 31, row = tid >> 5;
    const int b = m0 / HW;
    const int pix0 = m0 - b*HW;

#pragma unroll
    for (int r = 0; r < 4; r++) {
        int cl = row + r*8;
        tile[cl][lane] = x[(size_t)(b*CIN + c0 + cl)*HW + pix0 + lane];
    }
    __syncthreads();
#pragma unroll
    for (int r = 0; r < 4; r++) {
        int pl = row + r*8;
        g_xt[(size_t)(m0 + pl)*CIN + c0 + lane] = tile[lane][pl];
    }
}

// ---------------------------------------------------------------- main weight repack (+ stats zero)
// layout: [k16][ngpair(16)][lane][4 words]; word w: ng = pr*2+(w>>1), j = w&1
__global__ void repack_w_kernel(const float* __restrict__ cw) {
    if (blockIdx.x == 0 && threadIdx.x < NGRP*BB*2) g_stats[threadIdx.x] = 0.f;
    int idx = blockIdx.x * 256 + threadIdx.x;   // over NK16*16*32*4 = 294912
    if (idx >= NK16*16*32*4) return;
    int w4   = idx & 3;
    int lane = (idx >> 2) & 31;
    int pr   = (idx >> 7) & 15;
    int k16  = idx >> 11;
    int ng = pr*2 + (w4 >> 1);
    int j  = w4 & 1;
    int kk0 = k16*16 + j*8 + 2*(lane & 3);
    int n   = ng*8 + (lane >> 2);
    int c0 = kk0 & 255, tap0 = kk0 >> 8;
    int kk1 = kk0 + 1;
    int c1 = kk1 & 255, tap1 = kk1 >> 8;
    float v0 = cw[(n*CIN + c0)*9 + tap0];
    float v1 = cw[(n*CIN + c1)*9 + tap1];
    float h0 = __bfloat162float(__float2bfloat16(v0));
    float h1 = __bfloat162float(__float2bfloat16(v1));
    g_Wfbh[idx] = pack2_bf16(h0, h1);
    g_Wfbl[idx] = pack2_bf16(v0 - h0, v1 - h1);
}

// ---------------------------------------------------------------- offset weight repack
// [k16][ng(4)][lane][2]; n = ng*8 + lane>>2 (pad n>=18 with 0)
__global__ void repack_ow_kernel(const float* __restrict__ ow) {
    int idx = blockIdx.x * 256 + threadIdx.x;   // over NK16*4*32*2 = 36864
    if (idx >= NK16*4*32*2) return;
    int j    = idx & 1;
    int t    = idx >> 1;
    int lane = t & 31; t >>= 5;
    int ng   = t & 3;
    int k16  = t >> 2;
    int kk0 = k16*16 + j*8 + 2*(lane & 3);
    int n   = ng*8 + (lane >> 2);
    int c0 = kk0 & 255, tap0 = kk0 >> 8;
    int kk1 = kk0 + 1;
    int c1 = kk1 & 255, tap1 = kk1 >> 8;
    float v0 = (n < 18) ? ow[(n*CIN + c0)*9 + tap0] : 0.f;
    float v1 = (n < 18) ? ow[(n*CIN + c1)*9 + tap1] : 0.f;
    float h0 = __bfloat162float(__float2bfloat16(v0));
    float h1 = __bfloat162float(__float2bfloat16(v1));
    g_OWfh[idx] = pack2_bf16(h0, h1);
    g_OWfl[idx] = pack2_bf16(v0 - h0, v1 - h1);
}

// ---------------------------------------------------------------- offset conv as 3xBF16 GEMM
// M=18432 (BM=64, grid=288, 2 CTAs/SM), N=32 (18 real), K=2304. 256 threads =
// 8 warps = 4(wm) x 2(wn); warp tile 16 x 16; acc[2][4].
// Producer: thread = (row m_l = tid>>2, 8 channels cgrp = tid&3); shifted-window
// float4 loads from g_xt (zero-padded borders).
__global__ __launch_bounds__(256, 2) void offset_gemm_kernel(const float* __restrict__ ob) {
    __shared__ __align__(16) char asmb[2][8192];   // A: [ks(2)][wm(4)][1KB: 512 hi + 512 lo]
    __shared__ __align__(16) char bsmb[2][4096];   // B: [hi 2KB: [ks][ng4][lane][2]][lo 2KB]
    const int tid = threadIdx.x, lane = tid & 31, wid = tid >> 5;
    const int wm = wid & 3, wn = wid >> 2;
    const int m0 = blockIdx.x * 64;
    const int b = m0 / HW;

    float acc[2][4];
#pragma unroll
    for (int i = 0; i < 2; i++)
#pragma unroll
        for (int e = 0; e < 4; e++) acc[i][e] = 0.f;

    // producer identity
    const int m_l  = tid >> 2;          // 0..63
    const int cgrp = tid & 3;           // 8 channels
    const int p_ks = cgrp >> 1, p_jh = cgrp & 1;
    const int p_wm = m_l >> 4;
    const int p_px = (m_l >> 3) & 1;
    const int p_row = m_l & 7;
    const int mm = m0 + m_l;
    const int rem = mm - b*HW;
    const int h = rem / WW, w = rem - h*WW;

    int64_t gptr = 0;
    bool valid = false;
    auto tapParams = [&](int tap) {
        const int py = h - 1 + tap/3, pxx = w - 1 + tap%3;
        valid = (py >= 0) && (py < HH) && (pxx >= 0) && (pxx < WW);
        gptr = (int64_t)(b*HW + py*WW + pxx) * CIN;
    };

    float4 cv[2];
    auto loadG = [&](int q1) {
        const int c0s = ((q1 & 7) << 5) + p_ks*16 + p_jh*8;
        if (valid) {
            cv[0] = *reinterpret_cast<const float4*>(g_xt + gptr + c0s);
            cv[1] = *reinterpret_cast<const float4*>(g_xt + gptr + c0s + 4);
        } else {
            cv[0] = make_float4(0.f, 0.f, 0.f, 0.f);
            cv[1] = make_float4(0.f, 0.f, 0.f, 0.f);
        }
    };

    auto stsG = [&](int s) {
        char* base = asmb[s] + p_ks*4096 + p_wm*1024;
        const int woff = p_jh*8 + p_px*4;
#pragma unroll
        for (int f = 0; f < 2; f++) {
            float v0 = cv[f].x, v1 = cv[f].y, v2 = cv[f].z, v3 = cv[f].w;
            float h0 = __bfloat162float(__float2bfloat16(v0));
            float h1 = __bfloat162float(__float2bfloat16(v1));
            float h2 = __bfloat162float(__float2bfloat16(v2));
            float h3 = __bfloat162float(__float2bfloat16(v3));
            const int sl0 = p_row*4 + ((f*2)     ^ (p_row & 3));
            const int sl1 = p_row*4 + ((f*2 + 1) ^ (p_row & 3));
            *(uint32_t*)(base + sl0*16 + woff)       = pack2_bf16(h0, h1);
            *(uint32_t*)(base + sl1*16 + woff)       = pack2_bf16(h2, h3);
            *(uint32_t*)(base + 512 + sl0*16 + woff) = pack2_bf16(v0-h0, v1-h1);
            *(uint32_t*)(base + 512 + sl1*16 + woff) = pack2_bf16(v2-h2, v3-h3);
        }
    };

    const uint32_t bsb = smem_u32(bsmb);
    auto issueB = [&](int s, int q) {
        // per stage: hi 2KB (512 words) + lo 2KB; 128 threads each
        if (tid < 128) {
            CP_ASYNC16(bsb + s*4096 + tid*16, g_OWfh + (size_t)q*512 + tid*4);
        } else {
            CP_ASYNC16(bsb + s*4096 + 2048 + (tid - 128)*16, g_OWfl + (size_t)q*512 + (tid - 128)*4);
        }
    };

    const int lane_sw = lane ^ ((lane >> 2) & 3);

    auto mmaStep = [&](int p, int ks) {
        const char* ab = asmb[p] + ks*4096 + wm*1024 + lane_sw*16;
        uint4 h4 = *reinterpret_cast<const uint4*>(ab);
        uint4 l4 = *reinterpret_cast<const uint4*>(ab + 512);
        uint32_t ah[4] = {h4.x, h4.y, h4.z, h4.w};
        uint32_t al[4] = {l4.x, l4.y, l4.z, l4.w};
        const char* bb = bsmb[p] + ks*1024 + lane*8;
#pragma unroll
        for (int ng = 0; ng < 2; ng++) {
            const int ngg = wn*2 + ng;
            uint2 bh = *reinterpret_cast<const uint2*>(bb + ngg*256);
            uint2 bl = *reinterpret_cast<const uint2*>(bb + ngg*256 + 2048);
            MMA_BF16(acc[ng], ah, bh.x, bh.y);
            MMA_BF16(acc[ng], ah, bl.x, bl.y);
            MMA_BF16(acc[ng], al, bh.x, bh.y);
        }
    };

    // prologue
    tapParams(0);
    loadG(0);
    stsG(0);
    issueB(0, 0); CP_COMMIT();

    for (int q = 0; q < NST; q++) {
        const bool more = (q + 1 < NST);
        if (more && (((q + 1) & 7) == 0)) tapParams((q + 1) >> 3);
        if (more) loadG(q + 1);
        CP_WAIT0();
        __syncthreads();
        if (more) { issueB((q + 1) & 1, q + 1); CP_COMMIT(); }
        const int p = q & 1;
        mmaStep(p, 0);
        mmaStep(p, 1);
        if (more) stsG((q + 1) & 1);
    }

    // epilogue: offsets + bias (n < 18)
    const int mrow = m0 + wm*16 + (lane >> 2);
#pragma unroll
    for (int ng = 0; ng < 2; ng++) {
#pragma unroll
        for (int e = 0; e < 2; e++) {
            const int n = (wn*2 + ng)*8 + 2*(lane & 3) + e;
            if (n < 18) {
                const float bias = ob[n];
#pragma unroll
                for (int px = 0; px < 2; px++) {
                    const int m = mrow + px*8;
                    const int pr = m - b*HW;
                    g_off[(b*18 + n)*HW + pr] = acc[ng][px*2 + e] + bias;
                }
            }
        }
    }
}

// ---------------------------------------------------------------- fused gather + 3xBF16 GEMM + GN partials
// BM=64 (grid=288, 2 CTAs/SM), BN=256, BK=32, 256 threads (8 warps: wm=wid&1, wn=wid>>1).
#define B_STAGE 32768
#define A_BASE  65536
#define A_STG   8192
#define SRED_OFF 81920
#define SMEM_BYTES (81920 + 256)

__global__ __launch_bounds__(256, 2) void gemm_kernel() {
    extern __shared__ char smem[];
    float* sred = (float*)(smem + SRED_OFF);
    const uint32_t sb = smem_u32(smem);
    const int tid = threadIdx.x, lane = tid & 31, wid = tid >> 5;
    const int wm = wid & 1, wn = wid >> 1;
    const int m0 = blockIdx.x * 64;
    const int b = m0 / HW;

    if (tid < 64) sred[tid] = 0.f;

    float acc[2][8][4];
#pragma unroll
    for (int i = 0; i < 2; i++)
#pragma unroll
        for (int j = 0; j < 8; j++)
#pragma unroll
            for (int e = 0; e < 4; e++) acc[i][j][e] = 0.f;

    // ---- producer identity ----
    const int m_l  = tid >> 2;                 // 0..63
    const int cgrp = tid & 3;                  // channel group (8 ch)
    const int p_wm = (m_l >> 5) & 1;
    const int p_mt = (m_l >> 4) & 1;
    const int p_px = (m_l >> 3) & 1;
    const int p_row = m_l & 7;
    const int p_ks = cgrp >> 1, p_jh = cgrp & 1;
    const int mm = m0 + m_l;
    const int rem = mm - b*HW;
    const int h = rem / WW, w = rem - h*WW;

    uint32_t gib[4];
    float    gw[4];

    auto tapParams = [&](int tap) {
        const int obidx = ((b*18 + 2*tap)*HH + h)*WW + w;
        const float dy = g_off[obidx];
        const float dx = g_off[obidx + HW];
        const float sy = (float)(h - 1 + tap/3) + dy;
        const float sx = (float)(w - 1 + tap%3) + dx;
        const float y0f = floorf(sy), x0f = floorf(sx);
        const float fy = sy - y0f, fx = sx - x0f;
        const int y0 = (int)y0f, x0 = (int)x0f;
        const int y1 = y0 + 1,  x1 = x0 + 1;
        const bool vy0 = (y0 >= 0) && (y0 < HH), vy1 = (y1 >= 0) && (y1 < HH);
        const bool vx0 = (x0 >= 0) && (x0 < WW), vx1 = (x1 >= 0) && (x1 < WW);
        gw[0] = (vy0 && vx0) ? (1.f-fy)*(1.f-fx) : 0.f;
        gw[1] = (vy0 && vx1) ? (1.f-fy)*fx       : 0.f;
        gw[2] = (vy1 && vx0) ? fy*(1.f-fx)       : 0.f;
        gw[3] = (vy1 && vx1) ? fy*fx             : 0.f;
        const int cy0 = min(max(y0,0),HH-1), cy1 = min(max(y1,0),HH-1);
        const int cx0 = min(max(x0,0),WW-1), cx1 = min(max(x1,0),WW-1);
        gib[0] = (uint32_t)(b*HW + cy0*WW+cx0) * CIN;
        gib[1] = (uint32_t)(b*HW + cy0*WW+cx1) * CIN;
        gib[2] = (uint32_t)(b*HW + cy1*WW+cx0) * CIN;
        gib[3] = (uint32_t)(b*HW + cy1*WW+cx1) * CIN;
    };

    float4 cv[4];
    auto loadG = [&](int g, int q1) {
        const int cg = ((q1 & 7) << 5) + cgrp*8 + g*4;
#pragma unroll
        for (int c = 0; c < 4; c++)
            cv[c] = *reinterpret_cast<const float4*>(g_xt + (size_t)gib[c] + cg);
    };

    auto stsG = [&](int g, int s) {
        float v0 = gw[0]*cv[0].x + gw[1]*cv[1].x + gw[2]*cv[2].x + gw[3]*cv[3].x;
        float v1 = gw[0]*cv[0].y + gw[1]*cv[1].y + gw[2]*cv[2].y + gw[3]*cv[3].y;
        float v2 = gw[0]*cv[0].z + gw[1]*cv[1].z + gw[2]*cv[2].z + gw[3]*cv[3].z;
        float v3 = gw[0]*cv[0].w + gw[1]*cv[1].w + gw[2]*cv[2].w + gw[3]*cv[3].w;
        float h0 = __bfloat162float(__float2bfloat16(v0));
        float h1 = __bfloat162float(__float2bfloat16(v1));
        float h2 = __bfloat162float(__float2bfloat16(v2));
        float h3 = __bfloat162float(__float2bfloat16(v3));
        uint32_t hw0 = pack2_bf16(h0, h1),      hw1 = pack2_bf16(h2, h3);
        uint32_t lw0 = pack2_bf16(v0-h0, v1-h1), lw1 = pack2_bf16(v2-h2, v3-h3);
        char* base = smem + A_BASE + s*A_STG + p_ks*4096 + p_wm*2048 + p_mt*1024;
        const int woff = p_jh*8 + p_px*4;
        const int sl0 = p_row*4 + ((g*2)     ^ (p_row & 3));
        const int sl1 = p_row*4 + ((g*2 + 1) ^ (p_row & 3));
        *(uint32_t*)(base + sl0*16 + woff)       = hw0;
        *(uint32_t*)(base + sl1*16 + woff)       = hw1;
        *(uint32_t*)(base + 512 + sl0*16 + woff) = lw0;
        *(uint32_t*)(base + 512 + sl1*16 + woff) = lw1;
    };

    auto issueB = [&](int s, int q) {
        const uint32_t* srcH = g_Wfbh + (size_t)q * 4096;
        const uint32_t* srcL = g_Wfbl + (size_t)q * 4096;
        const uint32_t dH = sb + s*B_STAGE + tid*16;
#pragma unroll
        for (int j = 0; j < 4; j++) {
            CP_ASYNC16(dH + j*4096,         srcH + tid*4 + j*1024);
            CP_ASYNC16(dH + 16384 + j*4096, srcL + tid*4 + j*1024);
        }
    };

    const int lane_sw = lane ^ ((lane >> 2) & 3);

    auto mmaStep = [&](int p, int ks) {
        const char* ab = smem + A_BASE + p*A_STG + ks*4096 + wm*2048 + lane_sw*16;
        uint32_t ah[2][4], al[2][4];
#pragma unroll
        for (int mt = 0; mt < 2; mt++) {
            uint4 h4 = *reinterpret_cast<const uint4*>(ab + mt*1024);
            uint4 l4 = *reinterpret_cast<const uint4*>(ab + mt*1024 + 512);
            ah[mt][0] = h4.x; ah[mt][1] = h4.y; ah[mt][2] = h4.z; ah[mt][3] = h4.w;
            al[mt][0] = l4.x; al[mt][1] = l4.y; al[mt][2] = l4.z; al[mt][3] = l4.w;
        }
        const char* bb = smem + p*B_STAGE + ks*8192 + lane*16;
#pragma unroll
        for (int ntp = 0; ntp < 4; ntp++) {
            uint4 bh = *reinterpret_cast<const uint4*>(bb + (wn*4 + ntp)*512);
            uint4 bl = *reinterpret_cast<const uint4*>(bb + (wn*4 + ntp)*512 + 16384);
#pragma unroll
            for (int mt = 0; mt < 2; mt++) {
                MMA_BF16(acc[mt][ntp*2],     ah[mt], bh.x, bh.y);
                MMA_BF16(acc[mt][ntp*2],     ah[mt], bl.x, bl.y);
                MMA_BF16(acc[mt][ntp*2],     al[mt], bh.x, bh.y);
                MMA_BF16(acc[mt][ntp*2 + 1], ah[mt], bh.z, bh.w);
                MMA_BF16(acc[mt][ntp*2 + 1], ah[mt], bl.z, bl.w);
                MMA_BF16(acc[mt][ntp*2 + 1], al[mt], bh.z, bh.w);
            }
        }
    };

    // prologue
    tapParams(0);
    loadG(0, 0); stsG(0, 0);
    loadG(1, 0); stsG(1, 0);
    issueB(0, 0); CP_COMMIT();

    for (int q = 0; q < NST; q++) {
        CP_WAIT0();
        __syncthreads();
        const bool more = (q + 1 < NST);
        if (more) { issueB((q + 1) & 1, q + 1); CP_COMMIT(); }
        if (more && (((q + 1) & 7) == 0)) tapParams((q + 1) >> 3);
        const int p = q & 1;

        if (more) loadG(0, q + 1);
        mmaStep(p, 0);
        if (more) { stsG(0, (q + 1) & 1); loadG(1, q + 1); }
        mmaStep(p, 1);
        if (more) stsG(1, (q + 1) & 1);
    }

    // Epilogue: write g_O (NHWC) + GN partial sums
    const int mrow = m0 + wm*32 + (lane >> 2);
#pragma unroll
    for (int nt = 0; nt < 8; nt++) {
        const int ng = wn*8 + nt;
        const int n = wn*64 + nt*8 + 2*(lane & 3);
        float s = 0.f, s2 = 0.f;
#pragma unroll
        for (int mt = 0; mt < 2; mt++) {
            float* a4 = acc[mt][nt];
            const int m1 = mrow + mt*16;
            *reinterpret_cast<float2*>(&g_O[(size_t)m1*COUT + n])       = make_float2(a4[0], a4[1]);
            *reinterpret_cast<float2*>(&g_O[(size_t)(m1 + 8)*COUT + n]) = make_float2(a4[2], a4[3]);
            s  += a4[0] + a4[1] + a4[2] + a4[3];
            s2 += a4[0]*a4[0] + a4[1]*a4[1] + a4[2]*a4[2] + a4[3]*a4[3];
        }
#pragma unroll
        for (int o = 16; o > 0; o >>= 1) {
            s  += __shfl_down_sync(0xFFFFFFFFu, s,  o);
            s2 += __shfl_down_sync(0xFFFFFFFFu, s2, o);
        }
        if (lane == 0) {
            atomicAdd(&sred[ng*2 + 0], s);
            atomicAdd(&sred[ng*2 + 1], s2);
        }
    }
    __syncthreads();
    if (tid < 64) atomicAdd(&g_stats[b*64 + tid], sred[tid]);
}

// ---------------------------------------------------------------- GN + ReLU + NHWC->NCHW (smem transpose)
__global__ void norm_kernel(float* __restrict__ out,
                            const float* __restrict__ gamma,
                            const float* __restrict__ beta) {
    __shared__ float tile[32][33];
    const int m0 = blockIdx.x * 32;
    const int o0 = blockIdx.y * 32;
    const int tid = threadIdx.x;            // 256
    const int lane = tid & 31, row = tid >> 5;
    const int b = m0 / HW;

    const int o = o0 + lane;
    const int g = o >> 3;
    float s  = g_stats[(b*NGRP + g)*2 + 0];
    float s2 = g_stats[(b*NGRP + g)*2 + 1];
    float mu  = s  * (1.f / (float)GELEMS);
    float var = s2 * (1.f / (float)GELEMS) - mu*mu;
    float scale = rsqrtf(var + 1e-5f) * gamma[o];
    float shift = beta[o] - mu * scale;

#pragma unroll
    for (int r = 0; r < 4; r++) {
        int ml = r*8 + row;
        float v = g_O[(size_t)(m0 + ml)*COUT + o];
        tile[ml][lane] = fmaxf(fmaf(v, scale, shift), 0.f);
    }
    __syncthreads();
#pragma unroll
    for (int r = 0; r < 4; r++) {
        int ol = r*8 + row;
        int m = m0 + lane;
        out[(size_t)(b*COUT + o0 + ol)*HW + (m - b*HW)] = tile[lane][ol];
    }
}

// ---------------------------------------------------------------- launch
extern "C" void kernel_launch(void* const* d_in, const int* in_sizes, int n_in,
                              void* d_out, int out_size) {
    const float* x     = (const float*)d_in[0];
    const float* off_w = (const float*)d_in[1];
    const float* off_b = (const float*)d_in[2];
    const float* cw    = (const float*)d_in[3];
    const float* gamma = (const float*)d_in[4];
    const float* beta  = (const float*)d_in[5];
    float* out = (float*)d_out;

    cudaFuncSetAttribute(gemm_kernel,
                         cudaFuncAttributeMaxDynamicSharedMemorySize, SMEM_BYTES);

    transpose_kernel<<<dim3(MTOT/32, CIN/32), 256>>>(x);
    repack_w_kernel<<<(NK16*16*32*4 + 255)/256, 256>>>(cw);
    repack_ow_kernel<<<(NK16*4*32*2 + 255)/256, 256>>>(off_w);
    offset_gemm_kernel<<<MTOT/64, 256>>>(off_b);
    gemm_kernel<<<MTOT/64, 256, SMEM_BYTES>>>();
    norm_kernel<<<dim3(MTOT/32, COUT/32), 256>>>(out, gamma, beta);
}